// round 9
// baseline (speedup 1.0000x reference)
#include <cuda_runtime.h>
#include <cuda_bf16.h>
#include <math.h>
#include <stdint.h>

// ---------------- problem constants ----------------
#define BB   8
#define CC   384
#define HH   48
#define WW   48
#define NN   2304
#define NHH  12
#define NPP  4
#define HDD  32
#define SCALE_F 0.17677669529663687f

// ---------------- scratch ----------------
__device__ float g_cg   [BB*CC*NN];
__device__ float g_qt   [BB*CC*NN];
__device__ float g_kt   [BB*CC*NN];
__device__ float g_vt   [BB*CC*NN];
__device__ float g_dwt  [BB*CC*NN];     // dwconv out, [b][n][c]
__device__ float g_off  [BB*96*NN];
__device__ float g_pool [BB*CC*49];
__device__ float g_og   [BB*96*49];
__device__ float g_cbias[128];
__device__ __nv_bfloat16 g_wh [5*CC*CC];
__device__ __nv_bfloat16 g_wl [5*CC*CC];
__device__ __nv_bfloat16 g_wch[128*CC];
__device__ __nv_bfloat16 g_wcl[128*CC];
__device__ __nv_bfloat16 g_bh [BB*NN*CC];   // activations [b][n][c] hi (also attn out)
__device__ __nv_bfloat16 g_bl [BB*NN*CC];
__device__ __nv_bfloat16 g_xh [BB*NN*CC];   // ln2gelu out hi
__device__ __nv_bfloat16 g_xl [BB*NN*CC];

__device__ __forceinline__ float gelu_f(float x) {
    return 0.5f * x * (1.0f + erff(x * 0.7071067811865476f));
}
__device__ __forceinline__ uint32_t smem_u32(const void* p) {
    uint32_t a;
    asm("{ .reg .u64 t; cvta.to.shared.u64 t, %1; cvt.u32.u64 %0, t; }" : "=r"(a) : "l"(p));
    return a;
}
__device__ __forceinline__ void ldmx4(uint32_t* r, uint32_t addr) {
    asm volatile("ldmatrix.sync.aligned.m8n8.x4.shared.b16 {%0,%1,%2,%3}, [%4];"
        : "=r"(r[0]), "=r"(r[1]), "=r"(r[2]), "=r"(r[3]) : "r"(addr));
}
__device__ __forceinline__ void mma_bf16(float* d, const uint32_t* a, const uint32_t* b) {
    asm volatile("mma.sync.aligned.m16n8k16.row.col.f32.bf16.bf16.f32 "
        "{%0,%1,%2,%3}, {%4,%5,%6,%7}, {%8,%9}, {%0,%1,%2,%3};"
        : "+f"(d[0]), "+f"(d[1]), "+f"(d[2]), "+f"(d[3])
        : "r"(a[0]), "r"(a[1]), "r"(a[2]), "r"(a[3]), "r"(b[0]), "r"(b[1]));
}

// ---------------- bf16x3 tensor-core GEMM (256 thr, CTA 128x64, warp 32x32, 2 CTA/SM) ----------------
// out[o][n] = sum_c W[o][c] * Bt[b][n][c]
// omode 0: out [b,o,n] f32 (emode 0 none / 1 gelu / 2 batchnorm)
// omode 1: out [b,h,n,d] f32
// omode 2: offsets: rows o<96 -> off[b,96,n] = acc + bilerp(e0=og) + e1=cbias[o]
// smem buffer layout (per k-chunk buffer, 18432 B):
//   Ah @0 (128 rows x 48B), Al @6144, Bh @12288 (64 rows x 48B), Bl @15360
#define SMEM_DYN 36864
#define BUFB 18432u

__global__ __launch_bounds__(256) void gemm_mma(
    const __nv_bfloat16* __restrict__ Wh, const __nv_bfloat16* __restrict__ Wl,
    const __nv_bfloat16* __restrict__ Bth, const __nv_bfloat16* __restrict__ Btl,
    float* __restrict__ out, int omode, int emode,
    const float* __restrict__ e0, const float* __restrict__ e1,
    const float* __restrict__ e2, const float* __restrict__ e3)
{
    extern __shared__ char smem[];
    const uint32_t sb = smem_u32(smem);
    const int tid = threadIdx.x, wid = tid >> 5, lane = tid & 31;
    const int n0 = blockIdx.x * 64, o0 = blockIdx.y * 128, b = blockIdx.z;
    const int m0w = (wid & 3) * 32, n0w = (wid >> 2) * 32;

    // A loader: thread -> row (0..127), half (8 bf16 = uint4)
    const int larA = tid >> 1, lhA = tid & 1;
    const __nv_bfloat16* gAh = Wh + (size_t)(o0 + larA) * CC + lhA * 8;
    const __nv_bfloat16* gAl = Wl + (size_t)(o0 + larA) * CC + lhA * 8;
    const uint32_t stA = (uint32_t)(larA * 48 + lhA * 16);
    // B loader: thread -> row (0..63), quarter (4 bf16 = uint2)
    const int larB = tid >> 2, lqB = tid & 3;
    const __nv_bfloat16* gBh = Bth + ((size_t)b * NN + n0 + larB) * CC + lqB * 4;
    const __nv_bfloat16* gBl = Btl + ((size_t)b * NN + n0 + larB) * CC + lqB * 4;
    const uint32_t stB = (uint32_t)(larB * 48 + lqB * 8);

    const uint32_t aoff = (uint32_t)((m0w + (lane & 7) + ((lane >> 3) & 1) * 8) * 48
                                     + (lane >> 4) * 16);
    const uint32_t boff = (uint32_t)((n0w + (lane >> 4) * 8 + (lane & 7)) * 48
                                     + ((lane >> 3) & 1) * 16);

    float acc[2][4][4];
#pragma unroll
    for (int i = 0; i < 2; i++)
#pragma unroll
        for (int j = 0; j < 4; j++)
#pragma unroll
            for (int e = 0; e < 4; e++) acc[i][j][e] = 0.f;

    uint4 pAh = *(const uint4*)gAh;
    uint4 pAl = *(const uint4*)gAl;
    uint2 pBh = *(const uint2*)gBh;
    uint2 pBl = *(const uint2*)gBl;
    *(uint4*)(smem + stA)          = pAh;
    *(uint4*)(smem + 6144 + stA)   = pAl;
    *(uint2*)(smem + 12288 + stB)  = pBh;
    *(uint2*)(smem + 15360 + stB)  = pBl;
    __syncthreads();

    for (int kc = 0; kc < 24; kc++) {
        const uint32_t cur = (uint32_t)(kc & 1) * BUFB;
        if (kc < 23) {
            int ko = (kc + 1) * 16;
            pAh = *(const uint4*)(gAh + ko);
            pAl = *(const uint4*)(gAl + ko);
            pBh = *(const uint2*)(gBh + ko);
            pBl = *(const uint2*)(gBl + ko);
        }
        uint32_t ah[2][4], al[2][4], bfh[4][2], bfl[4][2];
#pragma unroll
        for (int mt = 0; mt < 2; mt++) {
            ldmx4(ah[mt], sb + cur + aoff + mt * 768);
            ldmx4(al[mt], sb + cur + 6144 + aoff + mt * 768);
        }
#pragma unroll
        for (int pr = 0; pr < 2; pr++) {
            uint32_t t[4];
            ldmx4(t, sb + cur + 12288 + boff + pr * 768);
            bfh[pr*2][0] = t[0]; bfh[pr*2][1] = t[1];
            bfh[pr*2+1][0] = t[2]; bfh[pr*2+1][1] = t[3];
            ldmx4(t, sb + cur + 15360 + boff + pr * 768);
            bfl[pr*2][0] = t[0]; bfl[pr*2][1] = t[1];
            bfl[pr*2+1][0] = t[2]; bfl[pr*2+1][1] = t[3];
        }
#pragma unroll
        for (int mt = 0; mt < 2; mt++)
#pragma unroll
            for (int nt = 0; nt < 4; nt++) {
                mma_bf16(acc[mt][nt], ah[mt], bfh[nt]);
                mma_bf16(acc[mt][nt], ah[mt], bfl[nt]);
                mma_bf16(acc[mt][nt], al[mt], bfh[nt]);
            }
        if (kc < 23) {
            const uint32_t nxt = (uint32_t)((kc + 1) & 1) * BUFB;
            *(uint4*)(smem + nxt + stA)         = pAh;
            *(uint4*)(smem + nxt + 6144 + stA)  = pAl;
            *(uint2*)(smem + nxt + 12288 + stB) = pBh;
            *(uint2*)(smem + nxt + 15360 + stB) = pBl;
        }
        __syncthreads();
    }

    if (omode == 0) {
        float* outb = out + (size_t)b * CC * NN;
#pragma unroll
        for (int mt = 0; mt < 2; mt++)
#pragma unroll
            for (int half = 0; half < 2; half++) {
                int o = o0 + m0w + mt * 16 + (lane >> 2) + half * 8;
                float s1 = 1.f, s0 = 0.f;
                if (emode == 2) {
                    float iv = rsqrtf(e3[o] + 1e-5f);
                    s1 = e0[o] * iv;
                    s0 = e1[o] - e2[o] * s1;
                }
#pragma unroll
                for (int nt = 0; nt < 4; nt++) {
                    float v0 = acc[mt][nt][half * 2 + 0];
                    float v1 = acc[mt][nt][half * 2 + 1];
                    if (emode == 1) { v0 = gelu_f(v0); v1 = gelu_f(v1); }
                    else if (emode == 2) { v0 = v0 * s1 + s0; v1 = v1 * s1 + s0; }
                    int n = n0 + n0w + nt * 8 + (lane & 3) * 2;
                    *(float2*)&outb[(size_t)o * NN + n] = make_float2(v0, v1);
                }
            }
    } else if (omode == 1) {
#pragma unroll
        for (int mt = 0; mt < 2; mt++)
#pragma unroll
            for (int half = 0; half < 2; half++) {
                int og2 = o0 + m0w + mt * 16 + (lane >> 2) + half * 8;
                int h = og2 >> 5, d = og2 & 31;
#pragma unroll
                for (int nt = 0; nt < 4; nt++) {
                    int n = n0 + n0w + nt * 8 + (lane & 3) * 2;
                    size_t bi = ((size_t)(b * NHH + h) * NN + n) * 32 + d;
                    out[bi]      = acc[mt][nt][half * 2 + 0];
                    out[bi + 32] = acc[mt][nt][half * 2 + 1];
                }
            }
    } else {
        const float* ogp_base = e0 + (size_t)b * 96 * 49;
#pragma unroll
        for (int mt = 0; mt < 2; mt++)
#pragma unroll
            for (int half = 0; half < 2; half++) {
                int o = m0w + mt * 16 + (lane >> 2) + half * 8;
                if (o >= 96) continue;
                float cbv = e1[o];
                const float* ogp = ogp_base + o * 49;
#pragma unroll
                for (int nt = 0; nt < 4; nt++) {
#pragma unroll
                    for (int dn = 0; dn < 2; dn++) {
                        int n = n0 + n0w + nt * 8 + (lane & 3) * 2 + dn;
                        int y = n / WW, x = n % WW;
                        float sy = fminf(fmaxf((y + 0.5f) * (7.0f / 48.0f) - 0.5f, 0.f), 6.f);
                        float sx = fminf(fmaxf((x + 0.5f) * (7.0f / 48.0f) - 0.5f, 0.f), 6.f);
                        int i0y = (int)floorf(sy); int i1y = min(i0y + 1, 6); float fy = sy - i0y;
                        int i0x = (int)floorf(sx); int i1x = min(i0x + 1, 6); float fx = sx - i0x;
                        float gv = (1.f - fy) * ((1.f - fx) * ogp[i0y * 7 + i0x] + fx * ogp[i0y * 7 + i1x])
                                 +        fy  * ((1.f - fx) * ogp[i1y * 7 + i0x] + fx * ogp[i1y * 7 + i1x]);
                        out[((size_t)b * 96 + o) * NN + n] = acc[mt][nt][half * 2 + dn] + gv + cbv;
                    }
                }
            }
    }
}

// ---------------- elementwise f32 -> bf16 hi/lo ----------------
__global__ void conv_hilo(const float* __restrict__ in,
                          __nv_bfloat16* __restrict__ oh,
                          __nv_bfloat16* __restrict__ ol)
{
    int i = (blockIdx.x * 256 + threadIdx.x) * 4;
    float4 v = *(const float4*)&in[i];
    __nv_bfloat16 h0 = __float2bfloat16(v.x), h1 = __float2bfloat16(v.y);
    __nv_bfloat16 h2 = __float2bfloat16(v.z), h3 = __float2bfloat16(v.w);
    __nv_bfloat16 l0 = __float2bfloat16(v.x - __bfloat162float(h0));
    __nv_bfloat16 l1 = __float2bfloat16(v.y - __bfloat162float(h1));
    __nv_bfloat16 l2 = __float2bfloat16(v.z - __bfloat162float(h2));
    __nv_bfloat16 l3 = __float2bfloat16(v.w - __bfloat162float(h3));
    __nv_bfloat16 hb[4] = {h0, h1, h2, h3};
    __nv_bfloat16 lb[4] = {l0, l1, l2, l3};
    *(uint2*)&oh[i] = *(uint2*)hb;
    *(uint2*)&ol[i] = *(uint2*)lb;
}

// ---------------- [b][c][n] f32 -> [b][n][c] bf16 hi/lo (transposing) ----------------
__global__ void convbt_kernel(const float* __restrict__ in,
                              __nv_bfloat16* __restrict__ oh,
                              __nv_bfloat16* __restrict__ ol)
{
    __shared__ float sm[64][33];
    int b = blockIdx.z;
    int c0 = blockIdx.y * 64;
    int n0 = blockIdx.x * 32;
    int tid = threadIdx.x;
#pragma unroll
    for (int i = 0; i < 2; i++) {
        int id = tid + 256 * i;
        int c = id >> 3, nch = id & 7;
        float4 v = *(const float4*)&in[((size_t)b * CC + c0 + c) * NN + n0 + nch * 4];
        sm[c][nch * 4 + 0] = v.x;
        sm[c][nch * 4 + 1] = v.y;
        sm[c][nch * 4 + 2] = v.z;
        sm[c][nch * 4 + 3] = v.w;
    }
    __syncthreads();
#pragma unroll
    for (int i = 0; i < 4; i++) {
        int id = tid + 256 * i;
        int n = id >> 5, cp = id & 31;
        int c = cp * 2;
        float x0 = sm[c][n], x1 = sm[c + 1][n];
        __nv_bfloat16 h0 = __float2bfloat16(x0), h1 = __float2bfloat16(x1);
        __nv_bfloat16 l0 = __float2bfloat16(x0 - __bfloat162float(h0));
        __nv_bfloat16 l1 = __float2bfloat16(x1 - __bfloat162float(h1));
        __nv_bfloat16 hb[2] = {h0, h1};
        __nv_bfloat16 lb[2] = {l0, l1};
        size_t o = ((size_t)b * NN + n0 + n) * CC + c0 + c;
        *(uint32_t*)&oh[o] = *(uint32_t*)hb;
        *(uint32_t*)&ol[o] = *(uint32_t*)lb;
    }
}

// ---------------- adaptive avg pool 48x48 -> 7x7 ----------------
__global__ void pool_kernel(const float* __restrict__ in, float* __restrict__ out)
{
    int idx = blockIdx.x * blockDim.x + threadIdx.x;
    if (idx >= BB * CC * 49) return;
    int p = idx % 7;
    int o = (idx / 7) % 7;
    int c = (idx / 49) % CC;
    int b = idx / (49 * CC);
    int sy = o * HH / 7, ey = ((o + 1) * HH + 6) / 7;
    int sx = p * WW / 7, ex = ((p + 1) * WW + 6) / 7;
    const float* f = in + ((size_t)b * CC + c) * NN;
    float s = 0.f;
    for (int y = sy; y < ey; y++)
        for (int x = sx; x < ex; x++)
            s += f[y * WW + x];
    out[idx] = s / (float)((ey - sy) * (ex - sx));
}

// ---------------- LN1 + W_post + W_off_guide fused -> og[b,96,49] ----------------
__global__ void ln1_post_og_kernel(const float* __restrict__ pool,
                                   const float* __restrict__ g1,
                                   const float* __restrict__ b1,
                                   const float* __restrict__ Wpost,
                                   const float* __restrict__ Woff,
                                   float* __restrict__ og)
{
    __shared__ float rs[CC], rq[CC], xn[CC];
    __shared__ float gsv[32];
    __shared__ float s_mu, s_rstd;
    int t = threadIdx.x;
    int b = blockIdx.x / 49;
    int s = blockIdx.x % 49;

    float x = pool[((size_t)b * CC + t) * 49 + s];
    rs[t] = x; rq[t] = x * x;
    __syncthreads();
    for (int st = 192; st >= 6; st >>= 1) {
        if (t < st) { rs[t] += rs[t + st]; rq[t] += rq[t + st]; }
        __syncthreads();
    }
    if (t == 0) {
        float a = 0.f, q = 0.f;
        for (int i = 0; i < 6; i++) { a += rs[i]; q += rq[i]; }
        float mu = a / CC;
        float var = q / CC - mu * mu;
        s_mu = mu; s_rstd = rsqrtf(var + 1e-6f);
    }
    __syncthreads();
    xn[t] = (x - s_mu) * s_rstd * g1[t] + b1[t];
    __syncthreads();
    if (t < 32) {
        float acc = 0.f;
        const float* wr = Wpost + (size_t)t * CC;
        for (int c = 0; c < CC; c++) acc += wr[c] * xn[c];
        gsv[t] = acc;
    }
    __syncthreads();
    if (t < 96) {
        float a = 0.f;
        const float* wr = Woff + (size_t)t * 64;
#pragma unroll
        for (int i = 0; i < 32; i++) a += wr[i] * gsv[i];
        og[((size_t)b * 96 + t) * 49 + s] = a;
    }
}

// ---------------- 3x3 depthwise conv + bias, writes [b][n][c] (padded smem) ----------------
__global__ void dwconv_t_kernel(const float* __restrict__ in,
                                const float* __restrict__ w,
                                const float* __restrict__ bias,
                                float* __restrict__ out)
{
    __shared__ float sin[3][64][49];
    __shared__ float sw[64][9];
    __shared__ float sbias[64];
    int c0 = blockIdx.x * 64;
    int y  = blockIdx.y;
    int b  = blockIdx.z;
    int tid = threadIdx.x;

    for (int id = tid; id < 3 * 64 * 48; id += 256) {
        int dy = id / (64 * 48);
        int r  = id % (64 * 48);
        int c = r / 48, x = r % 48;
        int ys = y + dy - 1;
        sin[dy][c][x] = (ys >= 0 && ys < HH)
            ? in[((size_t)b * CC + c0 + c) * NN + ys * WW + x] : 0.f;
    }
    for (int id = tid; id < 64 * 9; id += 256)
        sw[id / 9][id % 9] = w[(size_t)(c0 + id / 9) * 9 + id % 9];
    if (tid < 64) sbias[tid] = bias[c0 + tid];
    __syncthreads();

#pragma unroll
    for (int i = 0; i < 6; i++) {
        int id = tid + i * 256;
        int cp = id & 31, x = id >> 5;
        int c = cp * 2;
        float res[2];
#pragma unroll
        for (int cc = 0; cc < 2; cc++) {
            float s = 0.f;
#pragma unroll
            for (int dy = 0; dy < 3; dy++)
#pragma unroll
                for (int dx = 0; dx < 3; dx++) {
                    int xx = x + dx - 1;
                    if (xx >= 0 && xx < WW)
                        s += sin[dy][c + cc][xx] * sw[c + cc][dy * 3 + dx];
                }
            res[cc] = s + sbias[c + cc];
        }
        *(float2*)&out[((size_t)b * NN + y * WW + x) * CC + c0 + c] = make_float2(res[0], res[1]);
    }
}

// ---------------- LN2 + gelu on [b,n,c] -> bf16 hi/lo ----------------
__global__ void ln2gelu_kernel(const float* __restrict__ dwt,
                               const float* __restrict__ g2,
                               const float* __restrict__ b2,
                               __nv_bfloat16* __restrict__ xh,
                               __nv_bfloat16* __restrict__ xl)
{
    int gw = (blockIdx.x * blockDim.x + threadIdx.x) >> 5;
    int lane = threadIdx.x & 31;
    if (gw >= BB * NN) return;
    const float* row = dwt + (size_t)gw * CC;
    float2 v[6];
    float s = 0.f, q = 0.f;
#pragma unroll
    for (int j = 0; j < 6; j++) {
        v[j] = *(const float2*)&row[lane * 2 + 64 * j];
        s += v[j].x + v[j].y;
        q += v[j].x * v[j].x + v[j].y * v[j].y;
    }
#pragma unroll
    for (int st = 16; st > 0; st >>= 1) {
        s += __shfl_xor_sync(0xffffffffu, s, st);
        q += __shfl_xor_sync(0xffffffffu, q, st);
    }
    float mu = s / CC;
    float var = q / CC - mu * mu;
    float rstd = rsqrtf(var + 1e-6f);
#pragma unroll
    for (int j = 0; j < 6; j++) {
        int c = lane * 2 + 64 * j;
        float a0 = gelu_f((v[j].x - mu) * rstd * g2[c] + b2[c]);
        float a1 = gelu_f((v[j].y - mu) * rstd * g2[c + 1] + b2[c + 1]);
        __nv_bfloat16 h0 = __float2bfloat16(a0), h1 = __float2bfloat16(a1);
        __nv_bfloat16 l0 = __float2bfloat16(a0 - __bfloat162float(h0));
        __nv_bfloat16 l1 = __float2bfloat16(a1 - __bfloat162float(h1));
        __nv_bfloat16 hb[2] = {h0, h1};
        __nv_bfloat16 lb[2] = {l0, l1};
        size_t o = (size_t)gw * CC + c;
        *(uint32_t*)&xh[o] = *(uint32_t*)hb;
        *(uint32_t*)&xl[o] = *(uint32_t*)lb;
    }
}

// ---------------- Wcomb = Woff[:,32:64]@Wlo (bf16 hi/lo, padded to 128 rows) ----------------
__global__ void combinew_kernel(const float* __restrict__ Woff,
                                const float* __restrict__ Wlo,
                                const float* __restrict__ blo,
                                const float* __restrict__ boff,
                                __nv_bfloat16* __restrict__ wch,
                                __nv_bfloat16* __restrict__ wcl,
                                float* __restrict__ cbias)
{
    int o = blockIdx.x;
    int c = threadIdx.x;
    float acc = 0.f;
    if (o < 96) {
#pragma unroll
        for (int i = 0; i < 32; i++)
            acc += Woff[o * 64 + 32 + i] * Wlo[(size_t)i * CC + c];
    }
    __nv_bfloat16 h = __float2bfloat16(acc);
    __nv_bfloat16 l = __float2bfloat16(acc - __bfloat162float(h));
    wch[(size_t)o * CC + c] = h;
    wcl[(size_t)o * CC + c] = l;
    if (c == 0) {
        float s2 = 0.f;
        if (o < 96) {
            s2 = boff[o];
            for (int i = 0; i < 32; i++) s2 += Woff[o * 64 + 32 + i] * blo[i];
        }
        cbias[o] = s2;
    }
}

// ---------------- fused deformable attention ([b,h,n,d] in, bf16 hi/lo [b,n,c] out) ----------------
__global__ void attn_kernel(const float* __restrict__ qt,
                            const float* __restrict__ kt,
                            const float* __restrict__ vt,
                            const float* __restrict__ offb,
                            const float* __restrict__ abias,
                            __nv_bfloat16* __restrict__ aoh,
                            __nv_bfloat16* __restrict__ aol)
{
    int gw   = (blockIdx.x * blockDim.x + threadIdx.x) >> 5;
    int lane = threadIdx.x & 31;
    if (gw >= BB * NHH * NN) return;
    int n = gw % NN;
    int h = (gw / NN) % NHH;
    int b = gw / (NN * NHH);
    int qx = n % WW;
    int qy = n / WW;

    size_t head = (size_t)(b * NHH + h) * NN;
    const float* kf = kt + head * HDD;
    const float* vf = vt + head * HDD;
    float qv = qt[(head + n) * HDD + lane];

    float ov = 0.f;
    if (lane < 8) ov = offb[((size_t)(b * 96 + h * 8 + lane)) * NN + n];

    float sc[NPP], vs[NPP];
#pragma unroll
    for (int p = 0; p < NPP; p++) {
        float ox = __shfl_sync(0xffffffffu, ov, 2 * p);
        float oy = __shfl_sync(0xffffffffu, ov, 2 * p + 1);
        float gx = (((float)qx + 0.5f) / (float)WW + ox / (float)WW) * 2.0f - 1.0f;
        float gy = (((float)qy + 0.5f) / (float)HH + oy / (float)HH) * 2.0f - 1.0f;
        float x = (gx + 1.0f) * 0.5f * (float)WW - 0.5f;
        float y = (gy + 1.0f) * 0.5f * (float)HH - 0.5f;
        float x0f = floorf(x), y0f = floorf(y);
        float fx = x - x0f, fy = y - y0f;
        int x0 = (int)x0f, y0 = (int)y0f;
        int x1 = x0 + 1,  y1 = y0 + 1;
        bool vx0 = (x0 >= 0 && x0 < WW), vx1 = (x1 >= 0 && x1 < WW);
        bool vy0 = (y0 >= 0 && y0 < HH), vy1 = (y1 >= 0 && y1 < HH);
        float w00 = (1.f - fx) * (1.f - fy);
        float w01 = fx * (1.f - fy);
        float w10 = (1.f - fx) * fy;
        float w11 = fx * fy;

        float ks = 0.f, vsmp = 0.f;
        if (vx0 && vy0) { size_t i = (size_t)(y0 * WW + x0) * HDD + lane; ks += w00 * kf[i]; vsmp += w00 * vf[i]; }
        if (vx1 && vy0) { size_t i = (size_t)(y0 * WW + x1) * HDD + lane; ks += w01 * kf[i]; vsmp += w01 * vf[i]; }
        if (vx0 && vy1) { size_t i = (size_t)(y1 * WW + x0) * HDD + lane; ks += w10 * kf[i]; vsmp += w10 * vf[i]; }
        if (vx1 && vy1) { size_t i = (size_t)(y1 * WW + x1) * HDD + lane; ks += w11 * kf[i]; vsmp += w11 * vf[i]; }
        vs[p] = vsmp;

        float part = qv * ks;
#pragma unroll
        for (int s = 16; s > 0; s >>= 1)
            part += __shfl_xor_sync(0xffffffffu, part, s);

        int px = (int)rintf(x); px = min(max(px, 0), WW - 1);
        int py = (int)rintf(y); py = min(max(py, 0), HH - 1);
        int bidx = abs(qy - py) * WW + abs(qx - px);
        sc[p] = part * SCALE_F + abias[h * NN + bidx];
    }

    float m = fmaxf(fmaxf(sc[0], sc[1]), fmaxf(sc[2], sc[3]));
    float e0 = expf(sc[0] - m), e1 = expf(sc[1] - m),
          e2 = expf(sc[2] - m), e3 = expf(sc[3] - m);
    float denom = e0 + e1 + e2 + e3;
    float o = (e0 * vs[0] + e1 * vs[1] + e2 * vs[2] + e3 * vs[3]) / denom;

    __nv_bfloat16 hb = __float2bfloat16(o);
    __nv_bfloat16 lb = __float2bfloat16(o - __bfloat162float(hb));
    size_t oi = ((size_t)b * NN + n) * CC + h * HDD + lane;
    aoh[oi] = hb;
    aol[oi] = lb;
}

// ---------------- launch ----------------
extern "C" void kernel_launch(void* const* d_in, const int* in_sizes, int n_in,
                              void* d_out, int out_size)
{
    const float* local_feat    = (const float*)d_in[0];
    const float* context_prior = (const float*)d_in[1];
    const float* deformable_x  = (const float*)d_in[2];
    const float* W_q   = (const float*)d_in[3];
    const float* W_k   = (const float*)d_in[4];
    const float* W_v   = (const float*)d_in[5];
    const float* W_pre = (const float*)d_in[6];
    const float* ln1_g = (const float*)d_in[7];
    const float* ln1_b = (const float*)d_in[8];
    const float* W_post= (const float*)d_in[9];
    const float* dw_w  = (const float*)d_in[10];
    const float* dw_b  = (const float*)d_in[11];
    const float* ln2_g = (const float*)d_in[12];
    const float* ln2_b = (const float*)d_in[13];
    const float* W_lo  = (const float*)d_in[14];
    const float* b_lo  = (const float*)d_in[15];
    const float* W_off = (const float*)d_in[16];
    const float* b_off = (const float*)d_in[17];
    const float* abias = (const float*)d_in[18];
    const float* W_p   = (const float*)d_in[19];
    const float* bn_g  = (const float*)d_in[20];
    const float* bn_b  = (const float*)d_in[21];
    const float* bn_m  = (const float*)d_in[22];
    const float* bn_v  = (const float*)d_in[23];
    float* out = (float*)d_out;

    float *cg, *qt, *kt, *vt, *dwt, *off, *pool, *og, *cbias;
    __nv_bfloat16 *wh, *wl, *wch, *wcl, *bh, *bl, *xh, *xl;
    cudaGetSymbolAddress((void**)&cg,    g_cg);
    cudaGetSymbolAddress((void**)&qt,    g_qt);
    cudaGetSymbolAddress((void**)&kt,    g_kt);
    cudaGetSymbolAddress((void**)&vt,    g_vt);
    cudaGetSymbolAddress((void**)&dwt,   g_dwt);
    cudaGetSymbolAddress((void**)&off,   g_off);
    cudaGetSymbolAddress((void**)&pool,  g_pool);
    cudaGetSymbolAddress((void**)&og,    g_og);
    cudaGetSymbolAddress((void**)&cbias, g_cbias);
    cudaGetSymbolAddress((void**)&wh,    g_wh);
    cudaGetSymbolAddress((void**)&wl,    g_wl);
    cudaGetSymbolAddress((void**)&wch,   g_wch);
    cudaGetSymbolAddress((void**)&wcl,   g_wcl);
    cudaGetSymbolAddress((void**)&bh,    g_bh);
    cudaGetSymbolAddress((void**)&bl,    g_bl);
    cudaGetSymbolAddress((void**)&xh,    g_xh);
    cudaGetSymbolAddress((void**)&xl,    g_xl);

    static int smem_set = 0;
    if (!smem_set) {
        cudaFuncSetAttribute(gemm_mma, cudaFuncAttributeMaxDynamicSharedMemorySize, SMEM_DYN);
        smem_set = 1;
    }

    const int WSZ = CC * CC;
    const int WGRID = WSZ / 1024;
    dim3 gb(NN / 64, CC / 128, BB);             // (36, 3, 8)
    dim3 gboff(NN / 64, 1, BB);                 // (36, 1, 8)
    dim3 gt(NN / 32, CC / 64, BB);              // (72, 6, 8)

    // weights -> bf16 hi/lo (0:q 1:k 2:v 3:pre 4:p)
    conv_hilo<<<WGRID, 256>>>(W_q,   wh + 0 * WSZ, wl + 0 * WSZ);
    conv_hilo<<<WGRID, 256>>>(W_k,   wh + 1 * WSZ, wl + 1 * WSZ);
    conv_hilo<<<WGRID, 256>>>(W_v,   wh + 2 * WSZ, wl + 2 * WSZ);
    conv_hilo<<<WGRID, 256>>>(W_pre, wh + 3 * WSZ, wl + 3 * WSZ);
    conv_hilo<<<WGRID, 256>>>(W_p,   wh + 4 * WSZ, wl + 4 * WSZ);

    // offsets path front half
    dim3 gd(CC / 64, HH, BB);
    dwconv_t_kernel<<<gd, 256>>>(local_feat, dw_w, dw_b, dwt);
    ln2gelu_kernel<<<(BB * NN) / 8, 256>>>(dwt, ln2_g, ln2_b, xh, xl);
    combinew_kernel<<<128, CC>>>(W_off, W_lo, b_lo, b_off, wch, wcl, cbias);

    // q
    convbt_kernel<<<gt, 256>>>(local_feat, bh, bl);
    gemm_mma<<<gb, 256, SMEM_DYN>>>(wh + 0 * WSZ, wl + 0 * WSZ, bh, bl, qt, 1, 0,
                                    nullptr, nullptr, nullptr, nullptr);
    // k, cg
    convbt_kernel<<<gt, 256>>>(context_prior, bh, bl);
    gemm_mma<<<gb, 256, SMEM_DYN>>>(wh + 1 * WSZ, wl + 1 * WSZ, bh, bl, kt, 1, 0,
                                    nullptr, nullptr, nullptr, nullptr);
    gemm_mma<<<gb, 256, SMEM_DYN>>>(wh + 3 * WSZ, wl + 3 * WSZ, bh, bl, cg, 0, 1,
                                    nullptr, nullptr, nullptr, nullptr);
    // v
    convbt_kernel<<<gt, 256>>>(deformable_x, bh, bl);
    gemm_mma<<<gb, 256, SMEM_DYN>>>(wh + 2 * WSZ, wl + 2 * WSZ, bh, bl, vt, 1, 0,
                                    nullptr, nullptr, nullptr, nullptr);

    // guide path
    pool_kernel<<<(BB * CC * 49 + 255) / 256, 256>>>(cg, pool);
    ln1_post_og_kernel<<<BB * 49, CC>>>(pool, ln1_g, ln1_b, W_post, W_off, og);

    // offsets GEMM (tensor path, bilerp epilogue)
    gemm_mma<<<gboff, 256, SMEM_DYN>>>(wch, wcl, xh, xl, off, 2, 0,
                                       og, cbias, nullptr, nullptr);

    // attention -> bf16 hi/lo [b,n,c]
    attn_kernel<<<(BB * NHH * NN) / 8, 256>>>(qt, kt, vt, off, abias, bh, bl);

    // final projection + BN
    gemm_mma<<<gb, 256, SMEM_DYN>>>(wh + 4 * WSZ, wl + 4 * WSZ, bh, bl, out, 0, 2,
                                    bn_g, bn_b, bn_m, bn_v);
}

// round 11
// speedup vs baseline: 1.0250x; 1.0250x over previous
#include <cuda_runtime.h>
#include <cuda_bf16.h>
#include <math.h>
#include <stdint.h>

// ---------------- problem constants ----------------
#define BB   8
#define CC   384
#define HH   48
#define WW   48
#define NN   2304
#define NHH  12
#define NPP  4
#define HDD  32
#define SCALE_F 0.17677669529663687f

// ---------------- scratch ----------------
__device__ float g_cg   [BB*CC*NN];
__device__ float g_qt   [BB*CC*NN];
__device__ float g_kt   [BB*CC*NN];
__device__ float g_vt   [BB*CC*NN];
__device__ float g_dwt  [BB*CC*NN];     // dwconv out, [b][n][c]
__device__ float g_off  [BB*96*NN];
__device__ float g_pool [BB*CC*49];
__device__ float g_og   [BB*96*49];
__device__ float g_cbias[128];
__device__ __nv_bfloat16 g_wh [5*CC*CC];
__device__ __nv_bfloat16 g_wl [5*CC*CC];
__device__ __nv_bfloat16 g_wch[128*CC];
__device__ __nv_bfloat16 g_wcl[128*CC];
__device__ __nv_bfloat16 g_bh [BB*NN*CC];   // activations [b][n][c] hi (also attn out)
__device__ __nv_bfloat16 g_bl [BB*NN*CC];
__device__ __nv_bfloat16 g_xh [BB*NN*CC];   // ln2gelu out hi
__device__ __nv_bfloat16 g_xl [BB*NN*CC];

__device__ __forceinline__ float gelu_f(float x) {
    return 0.5f * x * (1.0f + erff(x * 0.7071067811865476f));
}
__device__ __forceinline__ uint32_t smem_u32(const void* p) {
    uint32_t a;
    asm("{ .reg .u64 t; cvta.to.shared.u64 t, %1; cvt.u32.u64 %0, t; }" : "=r"(a) : "l"(p));
    return a;
}
__device__ __forceinline__ void ldmx4(uint32_t* r, uint32_t addr) {
    asm volatile("ldmatrix.sync.aligned.m8n8.x4.shared.b16 {%0,%1,%2,%3}, [%4];"
        : "=r"(r[0]), "=r"(r[1]), "=r"(r[2]), "=r"(r[3]) : "r"(addr));
}
__device__ __forceinline__ void mma_bf16(float* d, const uint32_t* a, const uint32_t* b) {
    asm volatile("mma.sync.aligned.m16n8k16.row.col.f32.bf16.bf16.f32 "
        "{%0,%1,%2,%3}, {%4,%5,%6,%7}, {%8,%9}, {%0,%1,%2,%3};"
        : "+f"(d[0]), "+f"(d[1]), "+f"(d[2]), "+f"(d[3])
        : "r"(a[0]), "r"(a[1]), "r"(a[2]), "r"(a[3]), "r"(b[0]), "r"(b[1]));
}
__device__ __forceinline__ void cpasync16(uint32_t saddr, const void* gptr) {
    asm volatile("cp.async.cg.shared.global [%0], [%1], 16;"
        :: "r"(saddr), "l"(gptr) : "memory");
}
#define CP_COMMIT() asm volatile("cp.async.commit_group;" ::: "memory")
#define CP_WAIT1()  asm volatile("cp.async.wait_group 1;" ::: "memory")

// ---------------- bf16x3 tensor-core GEMM (R8 shape + cp.async 3-stage pipeline) ----------------
// out[o][n] = sum_c W[o][c] * Bt[b][n][c]
// omode 0: out [b,o,n] f32 (emode 0 none / 1 gelu / 2 batchnorm)
// omode 1: out [b,h,n,d] f32
// omode 2: offsets: rows o<96 -> off[b,96,n] = acc + bilerp(e0=og) + e1=cbias[o]
// per-stage buffer 24576 B: Ah @0, Al @6144, Bh @12288, Bl @18432 (rows 48B stride)
#define NSTAGE 3
#define STAGEB 24576u
#define SMEM_DYN (NSTAGE * 24576)

__global__ __launch_bounds__(256) void gemm_mma(
    const __nv_bfloat16* __restrict__ Wh, const __nv_bfloat16* __restrict__ Wl,
    const __nv_bfloat16* __restrict__ Bth, const __nv_bfloat16* __restrict__ Btl,
    float* __restrict__ out, int omode, int emode,
    const float* __restrict__ e0, const float* __restrict__ e1,
    const float* __restrict__ e2, const float* __restrict__ e3)
{
    extern __shared__ char smem[];
    const uint32_t sb = smem_u32(smem);
    const int tid = threadIdx.x, wid = tid >> 5, lane = tid & 31;
    const int n0 = blockIdx.x * 128, o0 = blockIdx.y * 128, b = blockIdx.z;
    const int m0w = (wid >> 2) * 64, n0w = (wid & 3) * 32;

    // loader: each thread owns one 16B chunk per tile-part per stage
    const int ldrow = tid >> 1, ldhalf = tid & 1;
    const __nv_bfloat16* gAh = Wh + (size_t)(o0 + ldrow) * CC + ldhalf * 8;
    const __nv_bfloat16* gAl = Wl + (size_t)(o0 + ldrow) * CC + ldhalf * 8;
    const __nv_bfloat16* gBh = Bth + ((size_t)b * NN + n0 + ldrow) * CC + ldhalf * 8;
    const __nv_bfloat16* gBl = Btl + ((size_t)b * NN + n0 + ldrow) * CC + ldhalf * 8;
    const uint32_t stoff = (uint32_t)(ldrow * 48 + ldhalf * 16);

    const uint32_t aoff = (uint32_t)((m0w + (lane & 7) + ((lane >> 3) & 1) * 8) * 48
                                     + (lane >> 4) * 16);
    const uint32_t boff = (uint32_t)((n0w + (lane >> 4) * 8 + (lane & 7)) * 48
                                     + ((lane >> 3) & 1) * 16);

    float acc[4][4][4];
#pragma unroll
    for (int i = 0; i < 4; i++)
#pragma unroll
        for (int j = 0; j < 4; j++)
#pragma unroll
            for (int e = 0; e < 4; e++) acc[i][j][e] = 0.f;

    // prologue: issue stages 0 and 1
#pragma unroll
    for (int s = 0; s < 2; s++) {
        uint32_t base = sb + s * STAGEB + stoff;
        int ko = s * 16;
        cpasync16(base,         gAh + ko);
        cpasync16(base + 6144,  gAl + ko);
        cpasync16(base + 12288, gBh + ko);
        cpasync16(base + 18432, gBl + ko);
        CP_COMMIT();
    }

    for (int kc = 0; kc < 24; kc++) {
        CP_WAIT1();              // stage kc arrived
        __syncthreads();         // all warps done with stage kc-1 (frees buf (kc+2)%3)

        if (kc + 2 < 24) {
            uint32_t base = sb + (uint32_t)((kc + 2) % NSTAGE) * STAGEB + stoff;
            int ko = (kc + 2) * 16;
            cpasync16(base,         gAh + ko);
            cpasync16(base + 6144,  gAl + ko);
            cpasync16(base + 12288, gBh + ko);
            cpasync16(base + 18432, gBl + ko);
        }
        CP_COMMIT();             // commit every iter so wait_group counts stay in sync

        const uint32_t cur = (uint32_t)(kc % NSTAGE) * STAGEB;
        uint32_t ah[4][4], al[4][4], bfh[4][2], bfl[4][2];
#pragma unroll
        for (int mt = 0; mt < 4; mt++) {
            ldmx4(ah[mt], sb + cur + aoff + mt * 768);
            ldmx4(al[mt], sb + cur + 6144 + aoff + mt * 768);
        }
#pragma unroll
        for (int pr = 0; pr < 2; pr++) {
            uint32_t t[4];
            ldmx4(t, sb + cur + 12288 + boff + pr * 768);
            bfh[pr*2][0] = t[0]; bfh[pr*2][1] = t[1];
            bfh[pr*2+1][0] = t[2]; bfh[pr*2+1][1] = t[3];
            ldmx4(t, sb + cur + 18432 + boff + pr * 768);
            bfl[pr*2][0] = t[0]; bfl[pr*2][1] = t[1];
            bfl[pr*2+1][0] = t[2]; bfl[pr*2+1][1] = t[3];
        }
#pragma unroll
        for (int mt = 0; mt < 4; mt++)
#pragma unroll
            for (int nt = 0; nt < 4; nt++) {
                mma_bf16(acc[mt][nt], ah[mt], bfh[nt]);
                mma_bf16(acc[mt][nt], ah[mt], bfl[nt]);
                mma_bf16(acc[mt][nt], al[mt], bfh[nt]);
            }
    }

    if (omode == 0) {
        float* outb = out + (size_t)b * CC * NN;
#pragma unroll
        for (int mt = 0; mt < 4; mt++)
#pragma unroll
            for (int half = 0; half < 2; half++) {
                int o = o0 + m0w + mt * 16 + (lane >> 2) + half * 8;
                float s1 = 1.f, s0 = 0.f;
                if (emode == 2) {
                    float iv = rsqrtf(e3[o] + 1e-5f);
                    s1 = e0[o] * iv;
                    s0 = e1[o] - e2[o] * s1;
                }
#pragma unroll
                for (int nt = 0; nt < 4; nt++) {
                    float v0 = acc[mt][nt][half * 2 + 0];
                    float v1 = acc[mt][nt][half * 2 + 1];
                    if (emode == 1) { v0 = gelu_f(v0); v1 = gelu_f(v1); }
                    else if (emode == 2) { v0 = v0 * s1 + s0; v1 = v1 * s1 + s0; }
                    int n = n0 + n0w + nt * 8 + (lane & 3) * 2;
                    *(float2*)&outb[(size_t)o * NN + n] = make_float2(v0, v1);
                }
            }
    } else if (omode == 1) {
#pragma unroll
        for (int mt = 0; mt < 4; mt++)
#pragma unroll
            for (int half = 0; half < 2; half++) {
                int og2 = o0 + m0w + mt * 16 + (lane >> 2) + half * 8;
                int h = og2 >> 5, d = og2 & 31;
#pragma unroll
                for (int nt = 0; nt < 4; nt++) {
                    int n = n0 + n0w + nt * 8 + (lane & 3) * 2;
                    size_t bi = ((size_t)(b * NHH + h) * NN + n) * 32 + d;
                    out[bi]      = acc[mt][nt][half * 2 + 0];
                    out[bi + 32] = acc[mt][nt][half * 2 + 1];
                }
            }
    } else {
        const float* ogp_base = e0 + (size_t)b * 96 * 49;
#pragma unroll
        for (int mt = 0; mt < 4; mt++)
#pragma unroll
            for (int half = 0; half < 2; half++) {
                int o = m0w + mt * 16 + (lane >> 2) + half * 8;
                if (o >= 96) continue;
                float cbv = e1[o];
                const float* ogp = ogp_base + o * 49;
#pragma unroll
                for (int nt = 0; nt < 4; nt++) {
#pragma unroll
                    for (int dn = 0; dn < 2; dn++) {
                        int n = n0 + n0w + nt * 8 + (lane & 3) * 2 + dn;
                        int y = n / WW, x = n % WW;
                        float sy = fminf(fmaxf((y + 0.5f) * (7.0f / 48.0f) - 0.5f, 0.f), 6.f);
                        float sx = fminf(fmaxf((x + 0.5f) * (7.0f / 48.0f) - 0.5f, 0.f), 6.f);
                        int i0y = (int)floorf(sy); int i1y = min(i0y + 1, 6); float fy = sy - i0y;
                        int i0x = (int)floorf(sx); int i1x = min(i0x + 1, 6); float fx = sx - i0x;
                        float gv = (1.f - fy) * ((1.f - fx) * ogp[i0y * 7 + i0x] + fx * ogp[i0y * 7 + i1x])
                                 +        fy  * ((1.f - fx) * ogp[i1y * 7 + i0x] + fx * ogp[i1y * 7 + i1x]);
                        out[((size_t)b * 96 + o) * NN + n] = acc[mt][nt][half * 2 + dn] + gv + cbv;
                    }
                }
            }
    }
}

// ---------------- elementwise f32 -> bf16 hi/lo ----------------
__global__ void conv_hilo(const float* __restrict__ in,
                          __nv_bfloat16* __restrict__ oh,
                          __nv_bfloat16* __restrict__ ol)
{
    int i = (blockIdx.x * 256 + threadIdx.x) * 4;
    float4 v = *(const float4*)&in[i];
    __nv_bfloat16 h0 = __float2bfloat16(v.x), h1 = __float2bfloat16(v.y);
    __nv_bfloat16 h2 = __float2bfloat16(v.z), h3 = __float2bfloat16(v.w);
    __nv_bfloat16 l0 = __float2bfloat16(v.x - __bfloat162float(h0));
    __nv_bfloat16 l1 = __float2bfloat16(v.y - __bfloat162float(h1));
    __nv_bfloat16 l2 = __float2bfloat16(v.z - __bfloat162float(h2));
    __nv_bfloat16 l3 = __float2bfloat16(v.w - __bfloat162float(h3));
    __nv_bfloat16 hb[4] = {h0, h1, h2, h3};
    __nv_bfloat16 lb[4] = {l0, l1, l2, l3};
    *(uint2*)&oh[i] = *(uint2*)hb;
    *(uint2*)&ol[i] = *(uint2*)lb;
}

// ---------------- [b][c][n] f32 -> [b][n][c] bf16 hi/lo (transposing) ----------------
__global__ void convbt_kernel(const float* __restrict__ in,
                              __nv_bfloat16* __restrict__ oh,
                              __nv_bfloat16* __restrict__ ol)
{
    __shared__ float sm[64][33];
    int b = blockIdx.z;
    int c0 = blockIdx.y * 64;
    int n0 = blockIdx.x * 32;
    int tid = threadIdx.x;
#pragma unroll
    for (int i = 0; i < 2; i++) {
        int id = tid + 256 * i;
        int c = id >> 3, nch = id & 7;
        float4 v = *(const float4*)&in[((size_t)b * CC + c0 + c) * NN + n0 + nch * 4];
        sm[c][nch * 4 + 0] = v.x;
        sm[c][nch * 4 + 1] = v.y;
        sm[c][nch * 4 + 2] = v.z;
        sm[c][nch * 4 + 3] = v.w;
    }
    __syncthreads();
#pragma unroll
    for (int i = 0; i < 4; i++) {
        int id = tid + 256 * i;
        int n = id >> 5, cp = id & 31;
        int c = cp * 2;
        float x0 = sm[c][n], x1 = sm[c + 1][n];
        __nv_bfloat16 h0 = __float2bfloat16(x0), h1 = __float2bfloat16(x1);
        __nv_bfloat16 l0 = __float2bfloat16(x0 - __bfloat162float(h0));
        __nv_bfloat16 l1 = __float2bfloat16(x1 - __bfloat162float(h1));
        __nv_bfloat16 hb[2] = {h0, h1};
        __nv_bfloat16 lb[2] = {l0, l1};
        size_t o = ((size_t)b * NN + n0 + n) * CC + c0 + c;
        *(uint32_t*)&oh[o] = *(uint32_t*)hb;
        *(uint32_t*)&ol[o] = *(uint32_t*)lb;
    }
}

// ---------------- adaptive avg pool 48x48 -> 7x7 ----------------
__global__ void pool_kernel(const float* __restrict__ in, float* __restrict__ out)
{
    int idx = blockIdx.x * blockDim.x + threadIdx.x;
    if (idx >= BB * CC * 49) return;
    int p = idx % 7;
    int o = (idx / 7) % 7;
    int c = (idx / 49) % CC;
    int b = idx / (49 * CC);
    int sy = o * HH / 7, ey = ((o + 1) * HH + 6) / 7;
    int sx = p * WW / 7, ex = ((p + 1) * WW + 6) / 7;
    const float* f = in + ((size_t)b * CC + c) * NN;
    float s = 0.f;
    for (int y = sy; y < ey; y++)
        for (int x = sx; x < ex; x++)
            s += f[y * WW + x];
    out[idx] = s / (float)((ey - sy) * (ex - sx));
}

// ---------------- LN1 + W_post + W_off_guide fused -> og[b,96,49] ----------------
__global__ void ln1_post_og_kernel(const float* __restrict__ pool,
                                   const float* __restrict__ g1,
                                   const float* __restrict__ b1,
                                   const float* __restrict__ Wpost,
                                   const float* __restrict__ Woff,
                                   float* __restrict__ og)
{
    __shared__ float rs[CC], rq[CC], xn[CC];
    __shared__ float gsv[32];
    __shared__ float s_mu, s_rstd;
    int t = threadIdx.x;
    int b = blockIdx.x / 49;
    int s = blockIdx.x % 49;

    float x = pool[((size_t)b * CC + t) * 49 + s];
    rs[t] = x; rq[t] = x * x;
    __syncthreads();
    for (int st = 192; st >= 6; st >>= 1) {
        if (t < st) { rs[t] += rs[t + st]; rq[t] += rq[t + st]; }
        __syncthreads();
    }
    if (t == 0) {
        float a = 0.f, q = 0.f;
        for (int i = 0; i < 6; i++) { a += rs[i]; q += rq[i]; }
        float mu = a / CC;
        float var = q / CC - mu * mu;
        s_mu = mu; s_rstd = rsqrtf(var + 1e-6f);
    }
    __syncthreads();
    xn[t] = (x - s_mu) * s_rstd * g1[t] + b1[t];
    __syncthreads();
    if (t < 32) {
        float acc = 0.f;
        const float* wr = Wpost + (size_t)t * CC;
        for (int c = 0; c < CC; c++) acc += wr[c] * xn[c];
        gsv[t] = acc;
    }
    __syncthreads();
    if (t < 96) {
        float a = 0.f;
        const float* wr = Woff + (size_t)t * 64;
#pragma unroll
        for (int i = 0; i < 32; i++) a += wr[i] * gsv[i];
        og[((size_t)b * 96 + t) * 49 + s] = a;
    }
}

// ---------------- 3x3 depthwise conv + bias, writes [b][n][c] (padded smem) ----------------
__global__ void dwconv_t_kernel(const float* __restrict__ in,
                                const float* __restrict__ w,
                                const float* __restrict__ bias,
                                float* __restrict__ out)
{
    __shared__ float sin[3][64][49];
    __shared__ float sw[64][9];
    __shared__ float sbias[64];
    int c0 = blockIdx.x * 64;
    int y  = blockIdx.y;
    int b  = blockIdx.z;
    int tid = threadIdx.x;

    for (int id = tid; id < 3 * 64 * 48; id += 256) {
        int dy = id / (64 * 48);
        int r  = id % (64 * 48);
        int c = r / 48, x = r % 48;
        int ys = y + dy - 1;
        sin[dy][c][x] = (ys >= 0 && ys < HH)
            ? in[((size_t)b * CC + c0 + c) * NN + ys * WW + x] : 0.f;
    }
    for (int id = tid; id < 64 * 9; id += 256)
        sw[id / 9][id % 9] = w[(size_t)(c0 + id / 9) * 9 + id % 9];
    if (tid < 64) sbias[tid] = bias[c0 + tid];
    __syncthreads();

#pragma unroll
    for (int i = 0; i < 6; i++) {
        int id = tid + i * 256;
        int cp = id & 31, x = id >> 5;
        int c = cp * 2;
        float res[2];
#pragma unroll
        for (int cc = 0; cc < 2; cc++) {
            float s = 0.f;
#pragma unroll
            for (int dy = 0; dy < 3; dy++)
#pragma unroll
                for (int dx = 0; dx < 3; dx++) {
                    int xx = x + dx - 1;
                    if (xx >= 0 && xx < WW)
                        s += sin[dy][c + cc][xx] * sw[c + cc][dy * 3 + dx];
                }
            res[cc] = s + sbias[c + cc];
        }
        *(float2*)&out[((size_t)b * NN + y * WW + x) * CC + c0 + c] = make_float2(res[0], res[1]);
    }
}

// ---------------- LN2 + gelu on [b,n,c] -> bf16 hi/lo ----------------
__global__ void ln2gelu_kernel(const float* __restrict__ dwt,
                               const float* __restrict__ g2,
                               const float* __restrict__ b2,
                               __nv_bfloat16* __restrict__ xh,
                               __nv_bfloat16* __restrict__ xl)
{
    int gw = (blockIdx.x * blockDim.x + threadIdx.x) >> 5;
    int lane = threadIdx.x & 31;
    if (gw >= BB * NN) return;
    const float* row = dwt + (size_t)gw * CC;
    float2 v[6];
    float s = 0.f, q = 0.f;
#pragma unroll
    for (int j = 0; j < 6; j++) {
        v[j] = *(const float2*)&row[lane * 2 + 64 * j];
        s += v[j].x + v[j].y;
        q += v[j].x * v[j].x + v[j].y * v[j].y;
    }
#pragma unroll
    for (int st = 16; st > 0; st >>= 1) {
        s += __shfl_xor_sync(0xffffffffu, s, st);
        q += __shfl_xor_sync(0xffffffffu, q, st);
    }
    float mu = s / CC;
    float var = q / CC - mu * mu;
    float rstd = rsqrtf(var + 1e-6f);
#pragma unroll
    for (int j = 0; j < 6; j++) {
        int c = lane * 2 + 64 * j;
        float a0 = gelu_f((v[j].x - mu) * rstd * g2[c] + b2[c]);
        float a1 = gelu_f((v[j].y - mu) * rstd * g2[c + 1] + b2[c + 1]);
        __nv_bfloat16 h0 = __float2bfloat16(a0), h1 = __float2bfloat16(a1);
        __nv_bfloat16 l0 = __float2bfloat16(a0 - __bfloat162float(h0));
        __nv_bfloat16 l1 = __float2bfloat16(a1 - __bfloat162float(h1));
        __nv_bfloat16 hb[2] = {h0, h1};
        __nv_bfloat16 lb[2] = {l0, l1};
        size_t o = (size_t)gw * CC + c;
        *(uint32_t*)&xh[o] = *(uint32_t*)hb;
        *(uint32_t*)&xl[o] = *(uint32_t*)lb;
    }
}

// ---------------- Wcomb = Woff[:,32:64]@Wlo (bf16 hi/lo, padded to 128 rows) ----------------
__global__ void combinew_kernel(const float* __restrict__ Woff,
                                const float* __restrict__ Wlo,
                                const float* __restrict__ blo,
                                const float* __restrict__ boff,
                                __nv_bfloat16* __restrict__ wch,
                                __nv_bfloat16* __restrict__ wcl,
                                float* __restrict__ cbias)
{
    int o = blockIdx.x;
    int c = threadIdx.x;
    float acc = 0.f;
    if (o < 96) {
#pragma unroll
        for (int i = 0; i < 32; i++)
            acc += Woff[o * 64 + 32 + i] * Wlo[(size_t)i * CC + c];
    }
    __nv_bfloat16 h = __float2bfloat16(acc);
    __nv_bfloat16 l = __float2bfloat16(acc - __bfloat162float(h));
    wch[(size_t)o * CC + c] = h;
    wcl[(size_t)o * CC + c] = l;
    if (c == 0) {
        float s2 = 0.f;
        if (o < 96) {
            s2 = boff[o];
            for (int i = 0; i < 32; i++) s2 += Woff[o * 64 + 32 + i] * blo[i];
        }
        cbias[o] = s2;
    }
}

// ---------------- fused deformable attention ([b,h,n,d] in, bf16 hi/lo [b,n,c] out) ----------------
__global__ void attn_kernel(const float* __restrict__ qt,
                            const float* __restrict__ kt,
                            const float* __restrict__ vt,
                            const float* __restrict__ offb,
                            const float* __restrict__ abias,
                            __nv_bfloat16* __restrict__ aoh,
                            __nv_bfloat16* __restrict__ aol)
{
    int gw   = (blockIdx.x * blockDim.x + threadIdx.x) >> 5;
    int lane = threadIdx.x & 31;
    if (gw >= BB * NHH * NN) return;
    int n = gw % NN;
    int h = (gw / NN) % NHH;
    int b = gw / (NN * NHH);
    int qx = n % WW;
    int qy = n / WW;

    size_t head = (size_t)(b * NHH + h) * NN;
    const float* kf = kt + head * HDD;
    const float* vf = vt + head * HDD;
    float qv = qt[(head + n) * HDD + lane];

    float ov = 0.f;
    if (lane < 8) ov = offb[((size_t)(b * 96 + h * 8 + lane)) * NN + n];

    float sc[NPP], vs[NPP];
#pragma unroll
    for (int p = 0; p < NPP; p++) {
        float ox = __shfl_sync(0xffffffffu, ov, 2 * p);
        float oy = __shfl_sync(0xffffffffu, ov, 2 * p + 1);
        float gx = (((float)qx + 0.5f) / (float)WW + ox / (float)WW) * 2.0f - 1.0f;
        float gy = (((float)qy + 0.5f) / (float)HH + oy / (float)HH) * 2.0f - 1.0f;
        float x = (gx + 1.0f) * 0.5f * (float)WW - 0.5f;
        float y = (gy + 1.0f) * 0.5f * (float)HH - 0.5f;
        float x0f = floorf(x), y0f = floorf(y);
        float fx = x - x0f, fy = y - y0f;
        int x0 = (int)x0f, y0 = (int)y0f;
        int x1 = x0 + 1,  y1 = y0 + 1;
        bool vx0 = (x0 >= 0 && x0 < WW), vx1 = (x1 >= 0 && x1 < WW);
        bool vy0 = (y0 >= 0 && y0 < HH), vy1 = (y1 >= 0 && y1 < HH);
        float w00 = (1.f - fx) * (1.f - fy);
        float w01 = fx * (1.f - fy);
        float w10 = (1.f - fx) * fy;
        float w11 = fx * fy;

        float ks = 0.f, vsmp = 0.f;
        if (vx0 && vy0) { size_t i = (size_t)(y0 * WW + x0) * HDD + lane; ks += w00 * kf[i]; vsmp += w00 * vf[i]; }
        if (vx1 && vy0) { size_t i = (size_t)(y0 * WW + x1) * HDD + lane; ks += w01 * kf[i]; vsmp += w01 * vf[i]; }
        if (vx0 && vy1) { size_t i = (size_t)(y1 * WW + x0) * HDD + lane; ks += w10 * kf[i]; vsmp += w10 * vf[i]; }
        if (vx1 && vy1) { size_t i = (size_t)(y1 * WW + x1) * HDD + lane; ks += w11 * kf[i]; vsmp += w11 * vf[i]; }
        vs[p] = vsmp;

        float part = qv * ks;
#pragma unroll
        for (int s = 16; s > 0; s >>= 1)
            part += __shfl_xor_sync(0xffffffffu, part, s);

        int px = (int)rintf(x); px = min(max(px, 0), WW - 1);
        int py = (int)rintf(y); py = min(max(py, 0), HH - 1);
        int bidx = abs(qy - py) * WW + abs(qx - px);
        sc[p] = part * SCALE_F + abias[h * NN + bidx];
    }

    float m = fmaxf(fmaxf(sc[0], sc[1]), fmaxf(sc[2], sc[3]));
    float e0 = expf(sc[0] - m), e1 = expf(sc[1] - m),
          e2 = expf(sc[2] - m), e3 = expf(sc[3] - m);
    float denom = e0 + e1 + e2 + e3;
    float o = (e0 * vs[0] + e1 * vs[1] + e2 * vs[2] + e3 * vs[3]) / denom;

    __nv_bfloat16 hb = __float2bfloat16(o);
    __nv_bfloat16 lb = __float2bfloat16(o - __bfloat162float(hb));
    size_t oi = ((size_t)b * NN + n) * CC + h * HDD + lane;
    aoh[oi] = hb;
    aol[oi] = lb;
}

// ---------------- launch ----------------
extern "C" void kernel_launch(void* const* d_in, const int* in_sizes, int n_in,
                              void* d_out, int out_size)
{
    const float* local_feat    = (const float*)d_in[0];
    const float* context_prior = (const float*)d_in[1];
    const float* deformable_x  = (const float*)d_in[2];
    const float* W_q   = (const float*)d_in[3];
    const float* W_k   = (const float*)d_in[4];
    const float* W_v   = (const float*)d_in[5];
    const float* W_pre = (const float*)d_in[6];
    const float* ln1_g = (const float*)d_in[7];
    const float* ln1_b = (const float*)d_in[8];
    const float* W_post= (const float*)d_in[9];
    const float* dw_w  = (const float*)d_in[10];
    const float* dw_b  = (const float*)d_in[11];
    const float* ln2_g = (const float*)d_in[12];
    const float* ln2_b = (const float*)d_in[13];
    const float* W_lo  = (const float*)d_in[14];
    const float* b_lo  = (const float*)d_in[15];
    const float* W_off = (const float*)d_in[16];
    const float* b_off = (const float*)d_in[17];
    const float* abias = (const float*)d_in[18];
    const float* W_p   = (const float*)d_in[19];
    const float* bn_g  = (const float*)d_in[20];
    const float* bn_b  = (const float*)d_in[21];
    const float* bn_m  = (const float*)d_in[22];
    const float* bn_v  = (const float*)d_in[23];
    float* out = (float*)d_out;

    float *cg, *qt, *kt, *vt, *dwt, *off, *pool, *og, *cbias;
    __nv_bfloat16 *wh, *wl, *wch, *wcl, *bh, *bl, *xh, *xl;
    cudaGetSymbolAddress((void**)&cg,    g_cg);
    cudaGetSymbolAddress((void**)&qt,    g_qt);
    cudaGetSymbolAddress((void**)&kt,    g_kt);
    cudaGetSymbolAddress((void**)&vt,    g_vt);
    cudaGetSymbolAddress((void**)&dwt,   g_dwt);
    cudaGetSymbolAddress((void**)&off,   g_off);
    cudaGetSymbolAddress((void**)&pool,  g_pool);
    cudaGetSymbolAddress((void**)&og,    g_og);
    cudaGetSymbolAddress((void**)&cbias, g_cbias);
    cudaGetSymbolAddress((void**)&wh,    g_wh);
    cudaGetSymbolAddress((void**)&wl,    g_wl);
    cudaGetSymbolAddress((void**)&wch,   g_wch);
    cudaGetSymbolAddress((void**)&wcl,   g_wcl);
    cudaGetSymbolAddress((void**)&bh,    g_bh);
    cudaGetSymbolAddress((void**)&bl,    g_bl);
    cudaGetSymbolAddress((void**)&xh,    g_xh);
    cudaGetSymbolAddress((void**)&xl,    g_xl);

    static int smem_set = 0;
    if (!smem_set) {
        cudaFuncSetAttribute(gemm_mma, cudaFuncAttributeMaxDynamicSharedMemorySize, SMEM_DYN);
        smem_set = 1;
    }

    const int WSZ = CC * CC;
    const int WGRID = WSZ / 1024;
    dim3 gb(NN / 128, CC / 128, BB);            // (18, 3, 8)
    dim3 gboff(NN / 128, 1, BB);                // (18, 1, 8)
    dim3 gt(NN / 32, CC / 64, BB);              // (72, 6, 8)

    // weights -> bf16 hi/lo (0:q 1:k 2:v 3:pre 4:p)
    conv_hilo<<<WGRID, 256>>>(W_q,   wh + 0 * WSZ, wl + 0 * WSZ);
    conv_hilo<<<WGRID, 256>>>(W_k,   wh + 1 * WSZ, wl + 1 * WSZ);
    conv_hilo<<<WGRID, 256>>>(W_v,   wh + 2 * WSZ, wl + 2 * WSZ);
    conv_hilo<<<WGRID, 256>>>(W_pre, wh + 3 * WSZ, wl + 3 * WSZ);
    conv_hilo<<<WGRID, 256>>>(W_p,   wh + 4 * WSZ, wl + 4 * WSZ);

    // offsets path front half
    dim3 gd(CC / 64, HH, BB);
    dwconv_t_kernel<<<gd, 256>>>(local_feat, dw_w, dw_b, dwt);
    ln2gelu_kernel<<<(BB * NN) / 8, 256>>>(dwt, ln2_g, ln2_b, xh, xl);
    combinew_kernel<<<128, CC>>>(W_off, W_lo, b_lo, b_off, wch, wcl, cbias);

    // q
    convbt_kernel<<<gt, 256>>>(local_feat, bh, bl);
    gemm_mma<<<gb, 256, SMEM_DYN>>>(wh + 0 * WSZ, wl + 0 * WSZ, bh, bl, qt, 1, 0,
                                    nullptr, nullptr, nullptr, nullptr);
    // k, cg
    convbt_kernel<<<gt, 256>>>(context_prior, bh, bl);
    gemm_mma<<<gb, 256, SMEM_DYN>>>(wh + 1 * WSZ, wl + 1 * WSZ, bh, bl, kt, 1, 0,
                                    nullptr, nullptr, nullptr, nullptr);
    gemm_mma<<<gb, 256, SMEM_DYN>>>(wh + 3 * WSZ, wl + 3 * WSZ, bh, bl, cg, 0, 1,
                                    nullptr, nullptr, nullptr, nullptr);
    // v
    convbt_kernel<<<gt, 256>>>(deformable_x, bh, bl);
    gemm_mma<<<gb, 256, SMEM_DYN>>>(wh + 2 * WSZ, wl + 2 * WSZ, bh, bl, vt, 1, 0,
                                    nullptr, nullptr, nullptr, nullptr);

    // guide path
    pool_kernel<<<(BB * CC * 49 + 255) / 256, 256>>>(cg, pool);
    ln1_post_og_kernel<<<BB * 49, CC>>>(pool, ln1_g, ln1_b, W_post, W_off, og);

    // offsets GEMM (tensor path, bilerp epilogue)
    gemm_mma<<<gboff, 256, SMEM_DYN>>>(wch, wcl, xh, xl, off, 2, 0,
                                       og, cbias, nullptr, nullptr);

    // attention -> bf16 hi/lo [b,n,c]
    attn_kernel<<<(BB * NHH * NN) / 8, 256>>>(qt, kt, vt, off, abias, bh, bl);

    // final projection + BN
    gemm_mma<<<gb, 256, SMEM_DYN>>>(wh + 4 * WSZ, wl + 4 * WSZ, bh, bl, out, 0, 2,
                                    bn_g, bn_b, bn_m, bn_v);
}

// round 12
// speedup vs baseline: 1.2049x; 1.1755x over previous
#include <cuda_runtime.h>
#include <cuda_bf16.h>
#include <math.h>
#include <stdint.h>

// ---------------- problem constants ----------------
#define BB   8
#define CC   384
#define HH   48
#define WW   48
#define NN   2304
#define NHH  12
#define NPP  4
#define HDD  32
#define SCALE_F 0.17677669529663687f
#define SLICE ((size_t)BB*NN*CC)

// ---------------- scratch ----------------
__device__ float g_cg   [BB*CC*NN];
__device__ float g_qt   [BB*CC*NN];
__device__ float g_kt   [BB*CC*NN];
__device__ float g_vt   [BB*CC*NN];
__device__ float g_dwt  [BB*CC*NN];
__device__ float g_off  [BB*96*NN];
__device__ float g_pool [BB*CC*49];
__device__ float g_og   [BB*96*49];
__device__ float g_cbias[128];
__device__ __nv_bfloat16 g_wh [5*CC*CC];
__device__ __nv_bfloat16 g_wl [5*CC*CC];
__device__ __nv_bfloat16 g_wch[128*CC];
__device__ __nv_bfloat16 g_wcl[128*CC];
__device__ __nv_bfloat16 g_bh [3*BB*NN*CC];   // slices: 0 local(+attn out), 1 context, 2 deformable
__device__ __nv_bfloat16 g_bl [3*BB*NN*CC];
__device__ __nv_bfloat16 g_xh [BB*NN*CC];
__device__ __nv_bfloat16 g_xl [BB*NN*CC];

__device__ __forceinline__ float gelu_f(float x) {
    return 0.5f * x * (1.0f + erff(x * 0.7071067811865476f));
}
__device__ __forceinline__ uint32_t smem_u32(const void* p) {
    uint32_t a;
    asm("{ .reg .u64 t; cvta.to.shared.u64 t, %1; cvt.u32.u64 %0, t; }" : "=r"(a) : "l"(p));
    return a;
}
__device__ __forceinline__ void ldmx4(uint32_t* r, uint32_t addr) {
    asm volatile("ldmatrix.sync.aligned.m8n8.x4.shared.b16 {%0,%1,%2,%3}, [%4];"
        : "=r"(r[0]), "=r"(r[1]), "=r"(r[2]), "=r"(r[3]) : "r"(addr));
}
__device__ __forceinline__ void mma_bf16(float* d, const uint32_t* a, const uint32_t* b) {
    asm volatile("mma.sync.aligned.m16n8k16.row.col.f32.bf16.bf16.f32 "
        "{%0,%1,%2,%3}, {%4,%5,%6,%7}, {%8,%9}, {%0,%1,%2,%3};"
        : "+f"(d[0]), "+f"(d[1]), "+f"(d[2]), "+f"(d[3])
        : "r"(a[0]), "r"(a[1]), "r"(a[2]), "r"(a[3]), "r"(b[0]), "r"(b[1]));
}

#define SMEM_DYN 49152

// ---------------- shared GEMM mainloop (R8 shape, register-staged, double buffer) ----------------
struct GemmAcc { float a[4][4][4]; };

__device__ __forceinline__ void gemm_mainloop(
    char* smem, uint32_t sb, int tid, int wid, int lane, int m0w, int n0w,
    const __nv_bfloat16* gAh, const __nv_bfloat16* gAl,
    const __nv_bfloat16* gBh, const __nv_bfloat16* gBl,
    uint32_t stoff, GemmAcc& acc)
{
    const uint32_t aoff = (uint32_t)((m0w + (lane & 7) + ((lane >> 3) & 1) * 8) * 48
                                     + (lane >> 4) * 16);
    const uint32_t boff = (uint32_t)((n0w + (lane >> 4) * 8 + (lane & 7)) * 48
                                     + ((lane >> 3) & 1) * 16);
    uint4 pAh = *(const uint4*)gAh;
    uint4 pAl = *(const uint4*)gAl;
    uint4 pBh = *(const uint4*)gBh;
    uint4 pBl = *(const uint4*)gBl;
    *(uint4*)(smem + stoff)         = pAh;
    *(uint4*)(smem + 6144  + stoff) = pAl;
    *(uint4*)(smem + 12288 + stoff) = pBh;
    *(uint4*)(smem + 18432 + stoff) = pBl;
    __syncthreads();

    for (int kc = 0; kc < 24; kc++) {
        const uint32_t cur = (uint32_t)(kc & 1) * 24576u;
        if (kc < 23) {
            int ko = (kc + 1) * 16;
            pAh = *(const uint4*)(gAh + ko);
            pAl = *(const uint4*)(gAl + ko);
            pBh = *(const uint4*)(gBh + ko);
            pBl = *(const uint4*)(gBl + ko);
        }
        uint32_t ah[4][4], al[4][4], bfh[4][2], bfl[4][2];
#pragma unroll
        for (int mt = 0; mt < 4; mt++) {
            ldmx4(ah[mt], sb + cur + aoff + mt * 768);
            ldmx4(al[mt], sb + cur + 6144 + aoff + mt * 768);
        }
#pragma unroll
        for (int pr = 0; pr < 2; pr++) {
            uint32_t t[4];
            ldmx4(t, sb + cur + 12288 + boff + pr * 768);
            bfh[pr*2][0] = t[0]; bfh[pr*2][1] = t[1];
            bfh[pr*2+1][0] = t[2]; bfh[pr*2+1][1] = t[3];
            ldmx4(t, sb + cur + 18432 + boff + pr * 768);
            bfl[pr*2][0] = t[0]; bfl[pr*2][1] = t[1];
            bfl[pr*2+1][0] = t[2]; bfl[pr*2+1][1] = t[3];
        }
#pragma unroll
        for (int mt = 0; mt < 4; mt++)
#pragma unroll
            for (int nt = 0; nt < 4; nt++) {
                mma_bf16(acc.a[mt][nt], ah[mt], bfh[nt]);
                mma_bf16(acc.a[mt][nt], ah[mt], bfl[nt]);
                mma_bf16(acc.a[mt][nt], al[mt], bfh[nt]);
            }
        if (kc < 23) {
            const uint32_t nxt = (uint32_t)((kc + 1) & 1) * 24576u;
            *(uint4*)(smem + nxt + stoff)         = pAh;
            *(uint4*)(smem + nxt + 6144  + stoff) = pAl;
            *(uint4*)(smem + nxt + 12288 + stoff) = pBh;
            *(uint4*)(smem + nxt + 18432 + stoff) = pBl;
        }
        __syncthreads();
    }
}

// ---------------- batched front GEMM: v=0 q, v=1 k, v=2 v, v=3 pre(+gelu) ----------------
__global__ __launch_bounds__(256) void gemm_front(
    const __nv_bfloat16* __restrict__ whb, const __nv_bfloat16* __restrict__ wlb,
    const __nv_bfloat16* __restrict__ bhb, const __nv_bfloat16* __restrict__ blb,
    float* __restrict__ qt, float* __restrict__ kt,
    float* __restrict__ vt, float* __restrict__ cg)
{
    extern __shared__ char smem[];
    const uint32_t sb = smem_u32(smem);
    const int tid = threadIdx.x, wid = tid >> 5, lane = tid & 31;
    const int n0 = blockIdx.x * 128, o0 = blockIdx.y * 128;
    const int v = blockIdx.z >> 3, b = blockIdx.z & 7;
    const int m0w = (wid >> 2) * 64, n0w = (wid & 3) * 32;

    const int bs = (v == 0) ? 0 : (v == 3 ? 1 : v);         // B slice
    const size_t wofs = (size_t)v * CC * CC;

    const int ldrow = tid >> 1, ldhalf = tid & 1;
    const __nv_bfloat16* gAh = whb + wofs + (size_t)(o0 + ldrow) * CC + ldhalf * 8;
    const __nv_bfloat16* gAl = wlb + wofs + (size_t)(o0 + ldrow) * CC + ldhalf * 8;
    const __nv_bfloat16* gBh = bhb + (size_t)bs * SLICE + ((size_t)b * NN + n0 + ldrow) * CC + ldhalf * 8;
    const __nv_bfloat16* gBl = blb + (size_t)bs * SLICE + ((size_t)b * NN + n0 + ldrow) * CC + ldhalf * 8;
    const uint32_t stoff = (uint32_t)(ldrow * 48 + ldhalf * 16);

    GemmAcc acc;
#pragma unroll
    for (int i = 0; i < 4; i++)
#pragma unroll
        for (int j = 0; j < 4; j++)
#pragma unroll
            for (int e = 0; e < 4; e++) acc.a[i][j][e] = 0.f;

    gemm_mainloop(smem, sb, tid, wid, lane, m0w, n0w, gAh, gAl, gBh, gBl, stoff, acc);

    if (v < 3) {
        float* outp = (v == 0) ? qt : (v == 1) ? kt : vt;
#pragma unroll
        for (int mt = 0; mt < 4; mt++)
#pragma unroll
            for (int half = 0; half < 2; half++) {
                int og2 = o0 + m0w + mt * 16 + (lane >> 2) + half * 8;
                int h = og2 >> 5, d = og2 & 31;
#pragma unroll
                for (int nt = 0; nt < 4; nt++) {
                    int n = n0 + n0w + nt * 8 + (lane & 3) * 2;
                    size_t bi = ((size_t)(b * NHH + h) * NN + n) * 32 + d;
                    outp[bi]      = acc.a[mt][nt][half * 2 + 0];
                    outp[bi + 32] = acc.a[mt][nt][half * 2 + 1];
                }
            }
    } else {
        float* outb = cg + (size_t)b * CC * NN;
#pragma unroll
        for (int mt = 0; mt < 4; mt++)
#pragma unroll
            for (int half = 0; half < 2; half++) {
                int o = o0 + m0w + mt * 16 + (lane >> 2) + half * 8;
#pragma unroll
                for (int nt = 0; nt < 4; nt++) {
                    float v0 = gelu_f(acc.a[mt][nt][half * 2 + 0]);
                    float v1 = gelu_f(acc.a[mt][nt][half * 2 + 1]);
                    int n = n0 + n0w + nt * 8 + (lane & 3) * 2;
                    *(float2*)&outb[(size_t)o * NN + n] = make_float2(v0, v1);
                }
            }
    }
}

// ---------------- generic GEMM (final W_p + offsets) ----------------
// omode 0: out [b,o,n] f32 (emode 2 batchnorm)
// omode 2: offsets epilogue
__global__ __launch_bounds__(256) void gemm_mma(
    const __nv_bfloat16* __restrict__ Wh, const __nv_bfloat16* __restrict__ Wl,
    const __nv_bfloat16* __restrict__ Bth, const __nv_bfloat16* __restrict__ Btl,
    float* __restrict__ out, int omode, int emode,
    const float* __restrict__ e0, const float* __restrict__ e1,
    const float* __restrict__ e2, const float* __restrict__ e3)
{
    extern __shared__ char smem[];
    const uint32_t sb = smem_u32(smem);
    const int tid = threadIdx.x, wid = tid >> 5, lane = tid & 31;
    const int n0 = blockIdx.x * 128, o0 = blockIdx.y * 128, b = blockIdx.z;
    const int m0w = (wid >> 2) * 64, n0w = (wid & 3) * 32;

    const int ldrow = tid >> 1, ldhalf = tid & 1;
    const __nv_bfloat16* gAh = Wh + (size_t)(o0 + ldrow) * CC + ldhalf * 8;
    const __nv_bfloat16* gAl = Wl + (size_t)(o0 + ldrow) * CC + ldhalf * 8;
    const __nv_bfloat16* gBh = Bth + ((size_t)b * NN + n0 + ldrow) * CC + ldhalf * 8;
    const __nv_bfloat16* gBl = Btl + ((size_t)b * NN + n0 + ldrow) * CC + ldhalf * 8;
    const uint32_t stoff = (uint32_t)(ldrow * 48 + ldhalf * 16);

    GemmAcc acc;
#pragma unroll
    for (int i = 0; i < 4; i++)
#pragma unroll
        for (int j = 0; j < 4; j++)
#pragma unroll
            for (int e = 0; e < 4; e++) acc.a[i][j][e] = 0.f;

    gemm_mainloop(smem, sb, tid, wid, lane, m0w, n0w, gAh, gAl, gBh, gBl, stoff, acc);

    if (omode == 0) {
        float* outb = out + (size_t)b * CC * NN;
#pragma unroll
        for (int mt = 0; mt < 4; mt++)
#pragma unroll
            for (int half = 0; half < 2; half++) {
                int o = o0 + m0w + mt * 16 + (lane >> 2) + half * 8;
                float s1 = 1.f, s0 = 0.f;
                if (emode == 2) {
                    float iv = rsqrtf(e3[o] + 1e-5f);
                    s1 = e0[o] * iv;
                    s0 = e1[o] - e2[o] * s1;
                }
#pragma unroll
                for (int nt = 0; nt < 4; nt++) {
                    float v0 = acc.a[mt][nt][half * 2 + 0];
                    float v1 = acc.a[mt][nt][half * 2 + 1];
                    if (emode == 1) { v0 = gelu_f(v0); v1 = gelu_f(v1); }
                    else if (emode == 2) { v0 = v0 * s1 + s0; v1 = v1 * s1 + s0; }
                    int n = n0 + n0w + nt * 8 + (lane & 3) * 2;
                    *(float2*)&outb[(size_t)o * NN + n] = make_float2(v0, v1);
                }
            }
    } else {
        const float* ogp_base = e0 + (size_t)b * 96 * 49;
#pragma unroll
        for (int mt = 0; mt < 4; mt++)
#pragma unroll
            for (int half = 0; half < 2; half++) {
                int o = m0w + mt * 16 + (lane >> 2) + half * 8;
                if (o >= 96) continue;
                float cbv = e1[o];
                const float* ogp = ogp_base + o * 49;
#pragma unroll
                for (int nt = 0; nt < 4; nt++) {
#pragma unroll
                    for (int dn = 0; dn < 2; dn++) {
                        int n = n0 + n0w + nt * 8 + (lane & 3) * 2 + dn;
                        int y = n / WW, x = n % WW;
                        float sy = fminf(fmaxf((y + 0.5f) * (7.0f / 48.0f) - 0.5f, 0.f), 6.f);
                        float sx = fminf(fmaxf((x + 0.5f) * (7.0f / 48.0f) - 0.5f, 0.f), 6.f);
                        int i0y = (int)floorf(sy); int i1y = min(i0y + 1, 6); float fy = sy - i0y;
                        int i0x = (int)floorf(sx); int i1x = min(i0x + 1, 6); float fx = sx - i0x;
                        float gv = (1.f - fy) * ((1.f - fx) * ogp[i0y * 7 + i0x] + fx * ogp[i0y * 7 + i1x])
                                 +        fy  * ((1.f - fx) * ogp[i1y * 7 + i0x] + fx * ogp[i1y * 7 + i1x]);
                        out[((size_t)b * 96 + o) * NN + n] = acc.a[mt][nt][half * 2 + dn] + gv + cbv;
                    }
                }
            }
    }
}

// ---------------- 5 weights f32 -> bf16 hi/lo in one launch ----------------
__global__ void conv_hilo5(const float* __restrict__ w0, const float* __restrict__ w1,
                           const float* __restrict__ w2, const float* __restrict__ w3,
                           const float* __restrict__ w4,
                           __nv_bfloat16* __restrict__ oh, __nv_bfloat16* __restrict__ ol)
{
    const int WSZ = CC * CC;
    int gi = blockIdx.x * 256 + threadIdx.x;
    int s = gi / (WSZ / 4);
    int r = gi % (WSZ / 4);
    const float* in = (s == 0) ? w0 : (s == 1) ? w1 : (s == 2) ? w2 : (s == 3) ? w3 : w4;
    int i = r * 4;
    float4 v = *(const float4*)&in[i];
    __nv_bfloat16 h0 = __float2bfloat16(v.x), h1 = __float2bfloat16(v.y);
    __nv_bfloat16 h2 = __float2bfloat16(v.z), h3 = __float2bfloat16(v.w);
    __nv_bfloat16 l0 = __float2bfloat16(v.x - __bfloat162float(h0));
    __nv_bfloat16 l1 = __float2bfloat16(v.y - __bfloat162float(h1));
    __nv_bfloat16 l2 = __float2bfloat16(v.z - __bfloat162float(h2));
    __nv_bfloat16 l3 = __float2bfloat16(v.w - __bfloat162float(h3));
    __nv_bfloat16 hb[4] = {h0, h1, h2, h3};
    __nv_bfloat16 lb[4] = {l0, l1, l2, l3};
    size_t o = (size_t)s * WSZ + i;
    *(uint2*)&oh[o] = *(uint2*)hb;
    *(uint2*)&ol[o] = *(uint2*)lb;
}

// ---------------- 3 inputs [b][c][n] f32 -> [b][n][c] bf16 hi/lo, one launch ----------------
__global__ void convbt3_kernel(const float* __restrict__ in0, const float* __restrict__ in1,
                               const float* __restrict__ in2,
                               __nv_bfloat16* __restrict__ oh, __nv_bfloat16* __restrict__ ol)
{
    __shared__ float sm[64][33];
    int z = blockIdx.z;
    int s = z >> 3, b = z & 7;
    const float* in = (s == 0) ? in0 : (s == 1) ? in1 : in2;
    int c0 = blockIdx.y * 64;
    int n0 = blockIdx.x * 32;
    int tid = threadIdx.x;
#pragma unroll
    for (int i = 0; i < 2; i++) {
        int id = tid + 256 * i;
        int c = id >> 3, nch = id & 7;
        float4 v = *(const float4*)&in[((size_t)b * CC + c0 + c) * NN + n0 + nch * 4];
        sm[c][nch * 4 + 0] = v.x;
        sm[c][nch * 4 + 1] = v.y;
        sm[c][nch * 4 + 2] = v.z;
        sm[c][nch * 4 + 3] = v.w;
    }
    __syncthreads();
#pragma unroll
    for (int i = 0; i < 4; i++) {
        int id = tid + 256 * i;
        int n = id >> 5, cp = id & 31;
        int c = cp * 2;
        float x0 = sm[c][n], x1 = sm[c + 1][n];
        __nv_bfloat16 h0 = __float2bfloat16(x0), h1 = __float2bfloat16(x1);
        __nv_bfloat16 l0 = __float2bfloat16(x0 - __bfloat162float(h0));
        __nv_bfloat16 l1 = __float2bfloat16(x1 - __bfloat162float(h1));
        __nv_bfloat16 hb[2] = {h0, h1};
        __nv_bfloat16 lb[2] = {l0, l1};
        size_t o = (size_t)s * SLICE + ((size_t)b * NN + n0 + n) * CC + c0 + c;
        *(uint32_t*)&oh[o] = *(uint32_t*)hb;
        *(uint32_t*)&ol[o] = *(uint32_t*)lb;
    }
}

// ---------------- adaptive avg pool 48x48 -> 7x7 ----------------
__global__ void pool_kernel(const float* __restrict__ in, float* __restrict__ out)
{
    int idx = blockIdx.x * blockDim.x + threadIdx.x;
    if (idx >= BB * CC * 49) return;
    int p = idx % 7;
    int o = (idx / 7) % 7;
    int c = (idx / 49) % CC;
    int b = idx / (49 * CC);
    int sy = o * HH / 7, ey = ((o + 1) * HH + 6) / 7;
    int sx = p * WW / 7, ex = ((p + 1) * WW + 6) / 7;
    const float* f = in + ((size_t)b * CC + c) * NN;
    float s = 0.f;
    for (int y = sy; y < ey; y++)
        for (int x = sx; x < ex; x++)
            s += f[y * WW + x];
    out[idx] = s / (float)((ey - sy) * (ex - sx));
}

// ---------------- LN1 + W_post + W_off_guide fused -> og[b,96,49] ----------------
__global__ void ln1_post_og_kernel(const float* __restrict__ pool,
                                   const float* __restrict__ g1,
                                   const float* __restrict__ b1,
                                   const float* __restrict__ Wpost,
                                   const float* __restrict__ Woff,
                                   float* __restrict__ og)
{
    __shared__ float rs[CC], rq[CC], xn[CC];
    __shared__ float gsv[32];
    __shared__ float s_mu, s_rstd;
    int t = threadIdx.x;
    int b = blockIdx.x / 49;
    int s = blockIdx.x % 49;

    float x = pool[((size_t)b * CC + t) * 49 + s];
    rs[t] = x; rq[t] = x * x;
    __syncthreads();
    for (int st = 192; st >= 6; st >>= 1) {
        if (t < st) { rs[t] += rs[t + st]; rq[t] += rq[t + st]; }
        __syncthreads();
    }
    if (t == 0) {
        float a = 0.f, q = 0.f;
        for (int i = 0; i < 6; i++) { a += rs[i]; q += rq[i]; }
        float mu = a / CC;
        float var = q / CC - mu * mu;
        s_mu = mu; s_rstd = rsqrtf(var + 1e-6f);
    }
    __syncthreads();
    xn[t] = (x - s_mu) * s_rstd * g1[t] + b1[t];
    __syncthreads();
    if (t < 32) {
        float acc = 0.f;
        const float* wr = Wpost + (size_t)t * CC;
        for (int c = 0; c < CC; c++) acc += wr[c] * xn[c];
        gsv[t] = acc;
    }
    __syncthreads();
    if (t < 96) {
        float a = 0.f;
        const float* wr = Woff + (size_t)t * 64;
#pragma unroll
        for (int i = 0; i < 32; i++) a += wr[i] * gsv[i];
        og[((size_t)b * 96 + t) * 49 + s] = a;
    }
}

// ---------------- 3x3 depthwise conv + bias, writes [b][n][c] (padded smem) ----------------
__global__ void dwconv_t_kernel(const float* __restrict__ in,
                                const float* __restrict__ w,
                                const float* __restrict__ bias,
                                float* __restrict__ out)
{
    __shared__ float sin[3][64][49];
    __shared__ float sw[64][9];
    __shared__ float sbias[64];
    int c0 = blockIdx.x * 64;
    int y  = blockIdx.y;
    int b  = blockIdx.z;
    int tid = threadIdx.x;

    for (int id = tid; id < 3 * 64 * 48; id += 256) {
        int dy = id / (64 * 48);
        int r  = id % (64 * 48);
        int c = r / 48, x = r % 48;
        int ys = y + dy - 1;
        sin[dy][c][x] = (ys >= 0 && ys < HH)
            ? in[((size_t)b * CC + c0 + c) * NN + ys * WW + x] : 0.f;
    }
    for (int id = tid; id < 64 * 9; id += 256)
        sw[id / 9][id % 9] = w[(size_t)(c0 + id / 9) * 9 + id % 9];
    if (tid < 64) sbias[tid] = bias[c0 + tid];
    __syncthreads();

#pragma unroll
    for (int i = 0; i < 6; i++) {
        int id = tid + i * 256;
        int cp = id & 31, x = id >> 5;
        int c = cp * 2;
        float res[2];
#pragma unroll
        for (int cc = 0; cc < 2; cc++) {
            float s = 0.f;
#pragma unroll
            for (int dy = 0; dy < 3; dy++)
#pragma unroll
                for (int dx = 0; dx < 3; dx++) {
                    int xx = x + dx - 1;
                    if (xx >= 0 && xx < WW)
                        s += sin[dy][c + cc][xx] * sw[c + cc][dy * 3 + dx];
                }
            res[cc] = s + sbias[c + cc];
        }
        *(float2*)&out[((size_t)b * NN + y * WW + x) * CC + c0 + c] = make_float2(res[0], res[1]);
    }
}

// ---------------- LN2 + gelu on [b,n,c] -> bf16 hi/lo ----------------
__global__ void ln2gelu_kernel(const float* __restrict__ dwt,
                               const float* __restrict__ g2,
                               const float* __restrict__ b2,
                               __nv_bfloat16* __restrict__ xh,
                               __nv_bfloat16* __restrict__ xl)
{
    int gw = (blockIdx.x * blockDim.x + threadIdx.x) >> 5;
    int lane = threadIdx.x & 31;
    if (gw >= BB * NN) return;
    const float* row = dwt + (size_t)gw * CC;
    float2 v[6];
    float s = 0.f, q = 0.f;
#pragma unroll
    for (int j = 0; j < 6; j++) {
        v[j] = *(const float2*)&row[lane * 2 + 64 * j];
        s += v[j].x + v[j].y;
        q += v[j].x * v[j].x + v[j].y * v[j].y;
    }
#pragma unroll
    for (int st = 16; st > 0; st >>= 1) {
        s += __shfl_xor_sync(0xffffffffu, s, st);
        q += __shfl_xor_sync(0xffffffffu, q, st);
    }
    float mu = s / CC;
    float var = q / CC - mu * mu;
    float rstd = rsqrtf(var + 1e-6f);
#pragma unroll
    for (int j = 0; j < 6; j++) {
        int c = lane * 2 + 64 * j;
        float a0 = gelu_f((v[j].x - mu) * rstd * g2[c] + b2[c]);
        float a1 = gelu_f((v[j].y - mu) * rstd * g2[c + 1] + b2[c + 1]);
        __nv_bfloat16 h0 = __float2bfloat16(a0), h1 = __float2bfloat16(a1);
        __nv_bfloat16 l0 = __float2bfloat16(a0 - __bfloat162float(h0));
        __nv_bfloat16 l1 = __float2bfloat16(a1 - __bfloat162float(h1));
        __nv_bfloat16 hb[2] = {h0, h1};
        __nv_bfloat16 lb[2] = {l0, l1};
        size_t o = (size_t)gw * CC + c;
        *(uint32_t*)&xh[o] = *(uint32_t*)hb;
        *(uint32_t*)&xl[o] = *(uint32_t*)lb;
    }
}

// ---------------- Wcomb = Woff[:,32:64]@Wlo (bf16 hi/lo, padded to 128 rows) ----------------
__global__ void combinew_kernel(const float* __restrict__ Woff,
                                const float* __restrict__ Wlo,
                                const float* __restrict__ blo,
                                const float* __restrict__ boff,
                                __nv_bfloat16* __restrict__ wch,
                                __nv_bfloat16* __restrict__ wcl,
                                float* __restrict__ cbias)
{
    int o = blockIdx.x;
    int c = threadIdx.x;
    float acc = 0.f;
    if (o < 96) {
#pragma unroll
        for (int i = 0; i < 32; i++)
            acc += Woff[o * 64 + 32 + i] * Wlo[(size_t)i * CC + c];
    }
    __nv_bfloat16 h = __float2bfloat16(acc);
    __nv_bfloat16 l = __float2bfloat16(acc - __bfloat162float(h));
    wch[(size_t)o * CC + c] = h;
    wcl[(size_t)o * CC + c] = l;
    if (c == 0) {
        float s2 = 0.f;
        if (o < 96) {
            s2 = boff[o];
            for (int i = 0; i < 32; i++) s2 += Woff[o * 64 + 32 + i] * blo[i];
        }
        cbias[o] = s2;
    }
}

// ---------------- fused deformable attention ([b,h,n,d] in, bf16 hi/lo [b,n,c] out) ----------------
__global__ void attn_kernel(const float* __restrict__ qt,
                            const float* __restrict__ kt,
                            const float* __restrict__ vt,
                            const float* __restrict__ offb,
                            const float* __restrict__ abias,
                            __nv_bfloat16* __restrict__ aoh,
                            __nv_bfloat16* __restrict__ aol)
{
    int gw   = (blockIdx.x * blockDim.x + threadIdx.x) >> 5;
    int lane = threadIdx.x & 31;
    if (gw >= BB * NHH * NN) return;
    int n = gw % NN;
    int h = (gw / NN) % NHH;
    int b = gw / (NN * NHH);
    int qx = n % WW;
    int qy = n / WW;

    size_t head = (size_t)(b * NHH + h) * NN;
    const float* kf = kt + head * HDD;
    const float* vf = vt + head * HDD;
    float qv = qt[(head + n) * HDD + lane];

    float ov = 0.f;
    if (lane < 8) ov = offb[((size_t)(b * 96 + h * 8 + lane)) * NN + n];

    float sc[NPP], vs[NPP];
#pragma unroll
    for (int p = 0; p < NPP; p++) {
        float ox = __shfl_sync(0xffffffffu, ov, 2 * p);
        float oy = __shfl_sync(0xffffffffu, ov, 2 * p + 1);
        float gx = (((float)qx + 0.5f) / (float)WW + ox / (float)WW) * 2.0f - 1.0f;
        float gy = (((float)qy + 0.5f) / (float)HH + oy / (float)HH) * 2.0f - 1.0f;
        float x = (gx + 1.0f) * 0.5f * (float)WW - 0.5f;
        float y = (gy + 1.0f) * 0.5f * (float)HH - 0.5f;
        float x0f = floorf(x), y0f = floorf(y);
        float fx = x - x0f, fy = y - y0f;
        int x0 = (int)x0f, y0 = (int)y0f;
        int x1 = x0 + 1,  y1 = y0 + 1;
        bool vx0 = (x0 >= 0 && x0 < WW), vx1 = (x1 >= 0 && x1 < WW);
        bool vy0 = (y0 >= 0 && y0 < HH), vy1 = (y1 >= 0 && y1 < HH);
        float w00 = (1.f - fx) * (1.f - fy);
        float w01 = fx * (1.f - fy);
        float w10 = (1.f - fx) * fy;
        float w11 = fx * fy;

        float ks = 0.f, vsmp = 0.f;
        if (vx0 && vy0) { size_t i = (size_t)(y0 * WW + x0) * HDD + lane; ks += w00 * kf[i]; vsmp += w00 * vf[i]; }
        if (vx1 && vy0) { size_t i = (size_t)(y0 * WW + x1) * HDD + lane; ks += w01 * kf[i]; vsmp += w01 * vf[i]; }
        if (vx0 && vy1) { size_t i = (size_t)(y1 * WW + x0) * HDD + lane; ks += w10 * kf[i]; vsmp += w10 * vf[i]; }
        if (vx1 && vy1) { size_t i = (size_t)(y1 * WW + x1) * HDD + lane; ks += w11 * kf[i]; vsmp += w11 * vf[i]; }
        vs[p] = vsmp;

        float part = qv * ks;
#pragma unroll
        for (int s = 16; s > 0; s >>= 1)
            part += __shfl_xor_sync(0xffffffffu, part, s);

        int px = (int)rintf(x); px = min(max(px, 0), WW - 1);
        int py = (int)rintf(y); py = min(max(py, 0), HH - 1);
        int bidx = abs(qy - py) * WW + abs(qx - px);
        sc[p] = part * SCALE_F + abias[h * NN + bidx];
    }

    float m = fmaxf(fmaxf(sc[0], sc[1]), fmaxf(sc[2], sc[3]));
    float e0 = expf(sc[0] - m), e1 = expf(sc[1] - m),
          e2 = expf(sc[2] - m), e3 = expf(sc[3] - m);
    float denom = e0 + e1 + e2 + e3;
    float o = (e0 * vs[0] + e1 * vs[1] + e2 * vs[2] + e3 * vs[3]) / denom;

    __nv_bfloat16 hb = __float2bfloat16(o);
    __nv_bfloat16 lb = __float2bfloat16(o - __bfloat162float(hb));
    size_t oi = ((size_t)b * NN + n) * CC + h * HDD + lane;
    aoh[oi] = hb;
    aol[oi] = lb;
}

// ---------------- launch ----------------
extern "C" void kernel_launch(void* const* d_in, const int* in_sizes, int n_in,
                              void* d_out, int out_size)
{
    const float* local_feat    = (const float*)d_in[0];
    const float* context_prior = (const float*)d_in[1];
    const float* deformable_x  = (const float*)d_in[2];
    const float* W_q   = (const float*)d_in[3];
    const float* W_k   = (const float*)d_in[4];
    const float* W_v   = (const float*)d_in[5];
    const float* W_pre = (const float*)d_in[6];
    const float* ln1_g = (const float*)d_in[7];
    const float* ln1_b = (const float*)d_in[8];
    const float* W_post= (const float*)d_in[9];
    const float* dw_w  = (const float*)d_in[10];
    const float* dw_b  = (const float*)d_in[11];
    const float* ln2_g = (const float*)d_in[12];
    const float* ln2_b = (const float*)d_in[13];
    const float* W_lo  = (const float*)d_in[14];
    const float* b_lo  = (const float*)d_in[15];
    const float* W_off = (const float*)d_in[16];
    const float* b_off = (const float*)d_in[17];
    const float* abias = (const float*)d_in[18];
    const float* W_p   = (const float*)d_in[19];
    const float* bn_g  = (const float*)d_in[20];
    const float* bn_b  = (const float*)d_in[21];
    const float* bn_m  = (const float*)d_in[22];
    const float* bn_v  = (const float*)d_in[23];
    float* out = (float*)d_out;

    float *cg, *qt, *kt, *vt, *dwt, *off, *pool, *og, *cbias;
    __nv_bfloat16 *wh, *wl, *wch, *wcl, *bh, *bl, *xh, *xl;
    cudaGetSymbolAddress((void**)&cg,    g_cg);
    cudaGetSymbolAddress((void**)&qt,    g_qt);
    cudaGetSymbolAddress((void**)&kt,    g_kt);
    cudaGetSymbolAddress((void**)&vt,    g_vt);
    cudaGetSymbolAddress((void**)&dwt,   g_dwt);
    cudaGetSymbolAddress((void**)&off,   g_off);
    cudaGetSymbolAddress((void**)&pool,  g_pool);
    cudaGetSymbolAddress((void**)&og,    g_og);
    cudaGetSymbolAddress((void**)&cbias, g_cbias);
    cudaGetSymbolAddress((void**)&wh,    g_wh);
    cudaGetSymbolAddress((void**)&wl,    g_wl);
    cudaGetSymbolAddress((void**)&wch,   g_wch);
    cudaGetSymbolAddress((void**)&wcl,   g_wcl);
    cudaGetSymbolAddress((void**)&bh,    g_bh);
    cudaGetSymbolAddress((void**)&bl,    g_bl);
    cudaGetSymbolAddress((void**)&xh,    g_xh);
    cudaGetSymbolAddress((void**)&xl,    g_xl);

    static int smem_set = 0;
    if (!smem_set) {
        cudaFuncSetAttribute(gemm_mma,  cudaFuncAttributeMaxDynamicSharedMemorySize, SMEM_DYN);
        cudaFuncSetAttribute(gemm_front, cudaFuncAttributeMaxDynamicSharedMemorySize, SMEM_DYN);
        smem_set = 1;
    }

    dim3 gb(NN / 128, CC / 128, BB);            // (18, 3, 8)
    dim3 gbf(NN / 128, CC / 128, 4 * BB);       // (18, 3, 32)
    dim3 gboff(NN / 128, 1, BB);                // (18, 1, 8)
    dim3 gt3(NN / 32, CC / 64, 3 * BB);         // (72, 6, 24)

    // all weights -> bf16 hi/lo, one launch
    conv_hilo5<<<5 * 144, 256>>>(W_q, W_k, W_v, W_pre, W_p, wh, wl);

    // offsets path front half
    dim3 gd(CC / 64, HH, BB);
    dwconv_t_kernel<<<gd, 256>>>(local_feat, dw_w, dw_b, dwt);
    ln2gelu_kernel<<<(BB * NN) / 8, 256>>>(dwt, ln2_g, ln2_b, xh, xl);
    combinew_kernel<<<128, CC>>>(W_off, W_lo, b_lo, b_off, wch, wcl, cbias);

    // all 3 inputs -> bf16 hi/lo [b,n,c], one launch
    convbt3_kernel<<<gt3, 256>>>(local_feat, context_prior, deformable_x, bh, bl);

    // q, k, v, cg in ONE launch (1728 CTAs)
    gemm_front<<<gbf, 256, SMEM_DYN>>>(wh, wl, bh, bl, qt, kt, vt, cg);

    // guide path
    pool_kernel<<<(BB * CC * 49 + 255) / 256, 256>>>(cg, pool);
    ln1_post_og_kernel<<<BB * 49, CC>>>(pool, ln1_g, ln1_b, W_post, W_off, og);

    // offsets GEMM (tensor path, bilerp epilogue)
    gemm_mma<<<gboff, 256, SMEM_DYN>>>(wch, wcl, xh, xl, off, 2, 0,
                                       og, cbias, nullptr, nullptr);

    // attention -> bf16 hi/lo into slice 0 (local slice no longer needed)
    attn_kernel<<<(BB * NHH * NN) / 8, 256>>>(qt, kt, vt, off, abias, bh, bl);

    // final projection + BN
    gemm_mma<<<gb, 256, SMEM_DYN>>>(wh + 4 * (size_t)CC * CC, wl + 4 * (size_t)CC * CC,
                                    bh, bl, out, 0, 2, bn_g, bn_b, bn_m, bn_v);
}